// round 7
// baseline (speedup 1.0000x reference)
#include <cuda_runtime.h>
#include <math.h>
#include <stdint.h>

constexpr int TOK = 4096;   // B*N tokens
constexpr int C   = 768;
constexpr int C3  = 2304;
constexpr int MD  = 3072;
constexpr int NH  = 12;
constexpr int HD  = 64;
constexpr int SEQ = 1024;
constexpr int BH  = 48;     // B*NH

// ---------------- scratch (device globals; no allocation allowed) ----------
__device__ float g_h1[TOK * C];
__device__ float g_qkv[TOK * C3];
__device__ float g_attn[TOK * C];
__device__ float g_x1[TOK * C];
__device__ float g_h2[TOK * C];
__device__ float g_mid[TOK * MD];

#define CP_ASYNC16(dst, src) \
    asm volatile("cp.async.cg.shared.global [%0], [%1], 16;\n" :: "r"(dst), "l"(src))
#define CP_COMMIT() asm volatile("cp.async.commit_group;\n" ::)
#define CP_WAIT1()  asm volatile("cp.async.wait_group 1;\n" ::)

// ---------------- LayerNorm: one block per row (768 cols, 256 thr) --------
__global__ void ln_kernel(const float* __restrict__ x, const float* __restrict__ g,
                          const float* __restrict__ b, float* __restrict__ out) {
    __shared__ float s1[256], s2[256];
    int row = blockIdx.x, t = threadIdx.x;
    const float* xr = x + (size_t)row * C;
    float v0 = xr[t], v1 = xr[t + 256], v2 = xr[t + 512];
    s1[t] = v0 + v1 + v2;
    s2[t] = v0 * v0 + v1 * v1 + v2 * v2;
    __syncthreads();
    for (int o = 128; o > 0; o >>= 1) {
        if (t < o) { s1[t] += s1[t + o]; s2[t] += s2[t + o]; }
        __syncthreads();
    }
    float mean = s1[0] * (1.0f / C);
    float var  = s2[0] * (1.0f / C) - mean * mean;
    float inv  = rsqrtf(var + 1e-5f);
    float* orow = out + (size_t)row * C;
    orow[t]       = (v0 - mean) * inv * g[t]       + b[t];
    orow[t + 256] = (v1 - mean) * inv * g[t + 256] + b[t + 256];
    orow[t + 512] = (v2 - mean) * inv * g[t + 512] + b[t + 512];
}

// ---------------- TF32 tensor-core GEMM, cp.async, BK=32, 2 stages --------
// 128x128 CTA tile, BK=32, 256 threads = 8 warps (4 in M x 2 in N),
// warp tile 32x64, mma.m16n8k8 tf32 fed raw fp32 bits (HW truncation).
// As[s][m][k] stride 36, Bs[s][k][n] stride 136 (conflict-free fragment LDS).
// 2 stages x 35840 B = 71680 B -> two CTAs per SM.
constexpr int STAGES = 2;
constexpr int BK = 32;
constexpr int A_STRIDE = 36;
constexpr int B_STRIDE = 136;
constexpr int A_STAGE_W = 128 * A_STRIDE;
constexpr int B_STAGE_W = BK * B_STRIDE;
constexpr int GEMM_SMEM = (STAGES * (A_STAGE_W + B_STAGE_W)) * 4;  // 71680 B

template <bool BIAS, bool GELU_ACT, int NRES>
__global__ __launch_bounds__(256, 2) void gemm_tc(
    const float* __restrict__ A, const float* __restrict__ B,
    const float* __restrict__ bias, const float* __restrict__ r1,
    const float* __restrict__ r2, float* __restrict__ Cout, int N, int K) {
    extern __shared__ uint32_t smem[];
    uint32_t* AsBase = smem;                               // [STAGES][128][36]
    uint32_t* BsBase = smem + STAGES * A_STAGE_W;          // [STAGES][32][136]

    const int tid = threadIdx.x;
    const int m0 = blockIdx.y * 128, n0 = blockIdx.x * 128;
    const int warp = tid >> 5, lane = tid & 31;
    const int wm = warp & 3, wn = warp >> 2;
    const int gid = lane >> 2, tig = lane & 3;

    // cp.async mapping: A: 128 rows x 32 floats, 2 thr/row, 4 x 16B each
    //                   B: 32 rows x 128 floats, 8 thr/row, 4 x 16B each
    const int arow = tid >> 1, acol = (tid & 1) * 16;    // +c*4, c=0..3
    const int brow = tid >> 3, bcol = (tid & 7) * 16;    // +c*4, c=0..3

    const float* agp = A + (size_t)(m0 + arow) * K + acol;
    const float* bgp = B + (size_t)brow * N + n0 + bcol;
    const uint32_t da0 = (uint32_t)__cvta_generic_to_shared(
        AsBase + (size_t)arow * A_STRIDE + acol);
    const uint32_t db0 = (uint32_t)__cvta_generic_to_shared(
        BsBase + (size_t)brow * B_STRIDE + bcol);

    float acc[2][8][4] = {};

    auto issue_stage = [&](int s, int k0) {
        uint32_t da = da0 + s * (A_STAGE_W * 4);
        const float* ap = agp + k0;
#pragma unroll
        for (int c = 0; c < 4; c++)
            CP_ASYNC16(da + c * 16, ap + c * 4);
        uint32_t db = db0 + s * (B_STAGE_W * 4);
        const float* bp = bgp + (size_t)k0 * N;
#pragma unroll
        for (int c = 0; c < 4; c++)
            CP_ASYNC16(db + c * 16, bp + c * 4);
    };

    auto mma_stage = [&](int s) {
        const uint32_t* As = AsBase + s * A_STAGE_W;
        const uint32_t* Bs = BsBase + s * B_STAGE_W;
#pragma unroll
        for (int kk = 0; kk < BK; kk += 8) {
            uint32_t af[2][4], bf[8][2];
#pragma unroll
            for (int mt = 0; mt < 2; mt++) {
                int mr = wm * 32 + mt * 16 + gid;
                const uint32_t* ar = As + mr * A_STRIDE + kk + tig;
                af[mt][0] = ar[0];
                af[mt][1] = ar[8 * A_STRIDE];
                af[mt][2] = ar[4];
                af[mt][3] = ar[8 * A_STRIDE + 4];
            }
#pragma unroll
            for (int nt = 0; nt < 8; nt++) {
                int nc = wn * 64 + nt * 8 + gid;
                const uint32_t* br = Bs + (kk + tig) * B_STRIDE + nc;
                bf[nt][0] = br[0];
                bf[nt][1] = br[4 * B_STRIDE];
            }
#pragma unroll
            for (int mt = 0; mt < 2; mt++)
#pragma unroll
                for (int nt = 0; nt < 8; nt++)
                    asm volatile(
                        "mma.sync.aligned.m16n8k8.row.col.f32.tf32.tf32.f32 "
                        "{%0,%1,%2,%3}, {%4,%5,%6,%7}, {%8,%9}, {%0,%1,%2,%3};"
                        : "+f"(acc[mt][nt][0]), "+f"(acc[mt][nt][1]),
                          "+f"(acc[mt][nt][2]), "+f"(acc[mt][nt][3])
                        : "r"(af[mt][0]), "r"(af[mt][1]), "r"(af[mt][2]), "r"(af[mt][3]),
                          "r"(bf[nt][0]), "r"(bf[nt][1]));
        }
    };

    const int nk = K / BK;
    issue_stage(0, 0);
    CP_COMMIT();
    issue_stage(1, BK);
    CP_COMMIT();
    for (int i = 0; i < nk; i++) {
        CP_WAIT1();
        __syncthreads();
        mma_stage(i & 1);
        __syncthreads();
        int kn = (i + 2) * BK;
        if (kn < K) {
            issue_stage(i & 1, kn);
            CP_COMMIT();
        }
    }

    // epilogue
#pragma unroll
    for (int mt = 0; mt < 2; mt++) {
        int r0 = m0 + wm * 32 + mt * 16 + gid;
#pragma unroll
        for (int nt = 0; nt < 8; nt++) {
            int col = n0 + wn * 64 + nt * 8 + tig * 2;
#pragma unroll
            for (int half = 0; half < 2; half++) {
                int row = r0 + half * 8;
                float v0 = acc[mt][nt][half * 2 + 0];
                float v1 = acc[mt][nt][half * 2 + 1];
                if (BIAS) { v0 += bias[col]; v1 += bias[col + 1]; }
                if (GELU_ACT) {
                    v0 = 0.5f * v0 * (1.0f + erff(v0 * 0.70710678118654752f));
                    v1 = 0.5f * v1 * (1.0f + erff(v1 * 0.70710678118654752f));
                }
                size_t idx = (size_t)row * N + col;
                if (NRES >= 1) { v0 += r1[idx]; v1 += r1[idx + 1]; }
                if (NRES >= 2) { v0 += r2[idx]; v1 += r2[idx + 1]; }
                *(float2*)&Cout[idx] = make_float2(v0, v1);
            }
        }
    }
}

// ---------------- fused flash attention (FFMA, unchanged) ------------------
constexpr int ATTN_SMEM = (64 * 68 + 64 * 68 + 64 * 64) * 4;

__global__ void attn_kernel() {
    extern __shared__ float sm[];
    float (*Qs)[68]  = (float(*)[68])sm;
    float (*KPs)[68] = (float(*)[68])(sm + 64 * 68);
    float (*Vs)[64]  = (float(*)[64])(sm + 2 * 64 * 68);

    int tid = threadIdx.x;
    int bh = blockIdx.y, b = bh / NH, h = bh - b * NH;
    int q0 = blockIdx.x * 64;
    int ty = tid >> 4, tx = tid & 15;
    int arow = tid >> 2, akk = (tid & 3) * 4;
    int vrow = tid >> 4, vcol = (tid & 15) * 4;

    const float* base = g_qkv + (size_t)b * SEQ * C3;
    const float* qb = base + h * HD;
    const float* kb = base + C + h * HD;
    const float* vb = base + 2 * C + h * HD;

#pragma unroll
    for (int k0 = 0; k0 < HD; k0 += 16) {
        float4 qv = *(const float4*)&qb[(size_t)(q0 + arow) * C3 + k0 + akk];
        Qs[k0 + akk + 0][arow] = qv.x; Qs[k0 + akk + 1][arow] = qv.y;
        Qs[k0 + akk + 2][arow] = qv.z; Qs[k0 + akk + 3][arow] = qv.w;
    }

    float acc_o[4][4] = {};
    float m_i[4] = {-1e30f, -1e30f, -1e30f, -1e30f};
    float l_i[4] = {};

    for (int kv0 = 0; kv0 < SEQ; kv0 += 64) {
        __syncthreads();
#pragma unroll
        for (int k0 = 0; k0 < HD; k0 += 16) {
            float4 kv = *(const float4*)&kb[(size_t)(kv0 + arow) * C3 + k0 + akk];
            KPs[k0 + akk + 0][arow] = kv.x; KPs[k0 + akk + 1][arow] = kv.y;
            KPs[k0 + akk + 2][arow] = kv.z; KPs[k0 + akk + 3][arow] = kv.w;
        }
#pragma unroll
        for (int kk0 = 0; kk0 < 64; kk0 += 16) {
            *(float4*)&Vs[kk0 + vrow][vcol] =
                *(const float4*)&vb[(size_t)(kv0 + kk0 + vrow) * C3 + vcol];
        }
        __syncthreads();

        float s[4][4] = {};
#pragma unroll
        for (int d = 0; d < HD; d++) {
            float4 a4 = *(const float4*)&Qs[d][ty * 4];
            float4 b4 = *(const float4*)&KPs[d][tx * 4];
            float ar[4] = {a4.x, a4.y, a4.z, a4.w};
            float br[4] = {b4.x, b4.y, b4.z, b4.w};
#pragma unroll
            for (int i = 0; i < 4; i++)
#pragma unroll
                for (int j = 0; j < 4; j++) s[i][j] += ar[i] * br[j];
        }

        float corr[4];
#pragma unroll
        for (int i = 0; i < 4; i++) {
            float mx = fmaxf(fmaxf(s[i][0], s[i][1]), fmaxf(s[i][2], s[i][3])) * 0.125f;
#pragma unroll
            for (int o = 8; o > 0; o >>= 1)
                mx = fmaxf(mx, __shfl_xor_sync(0xffffffffu, mx, o));
            float mn = fmaxf(m_i[i], mx);
            corr[i] = __expf(m_i[i] - mn);
            m_i[i] = mn;
            float rs = 0.f;
#pragma unroll
            for (int j = 0; j < 4; j++) {
                s[i][j] = __expf(s[i][j] * 0.125f - mn);
                rs += s[i][j];
            }
#pragma unroll
            for (int o = 8; o > 0; o >>= 1)
                rs += __shfl_xor_sync(0xffffffffu, rs, o);
            l_i[i] = l_i[i] * corr[i] + rs;
#pragma unroll
            for (int j = 0; j < 4; j++) acc_o[i][j] *= corr[i];
        }

        __syncthreads();
#pragma unroll
        for (int i = 0; i < 4; i++)
            *(float4*)&KPs[ty * 4 + i][tx * 4] = make_float4(s[i][0], s[i][1], s[i][2], s[i][3]);
        __syncthreads();

#pragma unroll 8
        for (int kk = 0; kk < 64; kk++) {
            float4 b4 = *(const float4*)&Vs[kk][tx * 4];
            float br[4] = {b4.x, b4.y, b4.z, b4.w};
#pragma unroll
            for (int i = 0; i < 4; i++) {
                float a = KPs[ty * 4 + i][kk];
#pragma unroll
                for (int j = 0; j < 4; j++) acc_o[i][j] += a * br[j];
            }
        }
    }

#pragma unroll
    for (int i = 0; i < 4; i++) {
        float inv = 1.0f / l_i[i];
#pragma unroll
        for (int j = 0; j < 4; j++)
            g_attn[(size_t)(b * SEQ + q0 + ty * 4 + i) * C + h * HD + tx * 4 + j] =
                acc_o[i][j] * inv;
    }
}

// ---------------- launch ---------------------------------------------------
extern "C" void kernel_launch(void* const* d_in, const int* in_sizes, int n_in,
                              void* d_out, int out_size) {
    const float* x    = (const float*)d_in[0];
    const float* ln1g = (const float*)d_in[1];
    const float* ln1b = (const float*)d_in[2];
    const float* wqkv = (const float*)d_in[3];
    const float* wout = (const float*)d_in[4];
    const float* bout = (const float*)d_in[5];
    const float* ln2g = (const float*)d_in[6];
    const float* ln2b = (const float*)d_in[7];
    const float* w1   = (const float*)d_in[8];
    const float* b1   = (const float*)d_in[9];
    const float* w2   = (const float*)d_in[10];
    const float* b2   = (const float*)d_in[11];
    float* out = (float*)d_out;

    float *h1, *qkvp, *attnp, *x1p, *h2p, *midp;
    cudaGetSymbolAddress((void**)&h1,    g_h1);
    cudaGetSymbolAddress((void**)&qkvp,  g_qkv);
    cudaGetSymbolAddress((void**)&attnp, g_attn);
    cudaGetSymbolAddress((void**)&x1p,   g_x1);
    cudaGetSymbolAddress((void**)&h2p,   g_h2);
    cudaGetSymbolAddress((void**)&midp,  g_mid);

    cudaFuncSetAttribute(attn_kernel, cudaFuncAttributeMaxDynamicSharedMemorySize,
                         ATTN_SMEM);
    cudaFuncSetAttribute(gemm_tc<false, false, 0>,
                         cudaFuncAttributeMaxDynamicSharedMemorySize, GEMM_SMEM);
    cudaFuncSetAttribute(gemm_tc<true, false, 2>,
                         cudaFuncAttributeMaxDynamicSharedMemorySize, GEMM_SMEM);
    cudaFuncSetAttribute(gemm_tc<true, true, 0>,
                         cudaFuncAttributeMaxDynamicSharedMemorySize, GEMM_SMEM);
    cudaFuncSetAttribute(gemm_tc<true, false, 1>,
                         cudaFuncAttributeMaxDynamicSharedMemorySize, GEMM_SMEM);

    // 1) h = LN1(x)
    ln_kernel<<<TOK, 256>>>(x, ln1g, ln1b, h1);
    // 2) qkv = h @ w_qkv
    gemm_tc<false, false, 0><<<dim3(C3 / 128, TOK / 128), 256, GEMM_SMEM>>>(
        h1, wqkv, nullptr, nullptr, nullptr, qkvp, C3, C);
    // 3) fused attention: softmax(QK^T/8) @ V
    attn_kernel<<<dim3(SEQ / 64, BH), 256, ATTN_SMEM>>>();
    // 4) x1 = x + h + attn @ w_out + b_out   (double residual)
    gemm_tc<true, false, 2><<<dim3(C / 128, TOK / 128), 256, GEMM_SMEM>>>(
        attnp, wout, bout, x, h1, x1p, C, C);
    // 5) h2 = LN2(x1)
    ln_kernel<<<TOK, 256>>>(x1p, ln2g, ln2b, h2p);
    // 6) mid = gelu(h2 @ w1 + b1)
    gemm_tc<true, true, 0><<<dim3(MD / 128, TOK / 128), 256, GEMM_SMEM>>>(
        h2p, w1, b1, nullptr, nullptr, midp, MD, C);
    // 7) out = x1 + mid @ w2 + b2
    gemm_tc<true, false, 1><<<dim3(C / 128, TOK / 128), 256, GEMM_SMEM>>>(
        midp, w2, b2, x1p, nullptr, out, C, MD);
}

// round 8
// speedup vs baseline: 1.4227x; 1.4227x over previous
#include <cuda_runtime.h>
#include <math.h>
#include <stdint.h>

constexpr int TOK = 4096;   // B*N tokens
constexpr int C   = 768;
constexpr int C3  = 2304;
constexpr int MD  = 3072;
constexpr int NH  = 12;
constexpr int HD  = 64;
constexpr int SEQ = 1024;
constexpr int BH  = 48;     // B*NH

// ---------------- scratch (device globals; no allocation allowed) ----------
__device__ float g_h1[TOK * C];
__device__ float g_qkv[TOK * C3];
__device__ float g_attn[TOK * C];
__device__ float g_x1[TOK * C];
__device__ float g_h2[TOK * C];
__device__ float g_mid[TOK * MD];

#define CP_ASYNC16(dst, src) \
    asm volatile("cp.async.cg.shared.global [%0], [%1], 16;\n" :: "r"(dst), "l"(src))
#define CP_COMMIT() asm volatile("cp.async.commit_group;\n" ::)
#define CP_WAIT2()  asm volatile("cp.async.wait_group 2;\n" ::)

__device__ __forceinline__ void mma_tf32(float* d, const uint32_t* a, const uint32_t* b) {
    asm volatile(
        "mma.sync.aligned.m16n8k8.row.col.f32.tf32.tf32.f32 "
        "{%0,%1,%2,%3}, {%4,%5,%6,%7}, {%8,%9}, {%0,%1,%2,%3};"
        : "+f"(d[0]), "+f"(d[1]), "+f"(d[2]), "+f"(d[3])
        : "r"(a[0]), "r"(a[1]), "r"(a[2]), "r"(a[3]), "r"(b[0]), "r"(b[1]));
}

// ---------------- LayerNorm: one block per row (768 cols, 256 thr) --------
__global__ void ln_kernel(const float* __restrict__ x, const float* __restrict__ g,
                          const float* __restrict__ b, float* __restrict__ out) {
    __shared__ float s1[256], s2[256];
    int row = blockIdx.x, t = threadIdx.x;
    const float* xr = x + (size_t)row * C;
    float v0 = xr[t], v1 = xr[t + 256], v2 = xr[t + 512];
    s1[t] = v0 + v1 + v2;
    s2[t] = v0 * v0 + v1 * v1 + v2 * v2;
    __syncthreads();
    for (int o = 128; o > 0; o >>= 1) {
        if (t < o) { s1[t] += s1[t + o]; s2[t] += s2[t + o]; }
        __syncthreads();
    }
    float mean = s1[0] * (1.0f / C);
    float var  = s2[0] * (1.0f / C) - mean * mean;
    float inv  = rsqrtf(var + 1e-5f);
    float* orow = out + (size_t)row * C;
    orow[t]       = (v0 - mean) * inv * g[t]       + b[t];
    orow[t + 256] = (v1 - mean) * inv * g[t + 256] + b[t + 256];
    orow[t + 512] = (v2 - mean) * inv * g[t + 512] + b[t + 512];
}

// ---------------- TF32 tensor-core GEMM, cp.async 4-stage (round-5 cfg) ----
constexpr int STAGES = 4;
constexpr int A_STRIDE = 20;
constexpr int B_STRIDE = 136;
constexpr int A_STAGE_W = 128 * A_STRIDE;
constexpr int B_STAGE_W = 16 * B_STRIDE;
constexpr int GEMM_SMEM = (STAGES * (A_STAGE_W + B_STAGE_W)) * 4;  // 75776 B

template <bool BIAS, bool GELU_ACT, int NRES>
__global__ __launch_bounds__(256, 2) void gemm_tc(
    const float* __restrict__ A, const float* __restrict__ B,
    const float* __restrict__ bias, const float* __restrict__ r1,
    const float* __restrict__ r2, float* __restrict__ Cout, int N, int K) {
    extern __shared__ uint32_t smem[];
    uint32_t* AsBase = smem;                               // [STAGES][128][20]
    uint32_t* BsBase = smem + STAGES * A_STAGE_W;          // [STAGES][16][136]

    const int tid = threadIdx.x;
    const int m0 = blockIdx.y * 128, n0 = blockIdx.x * 128;
    const int warp = tid >> 5, lane = tid & 31;
    const int wm = warp & 3, wn = warp >> 2;
    const int gid = lane >> 2, tig = lane & 3;

    const int arow = tid >> 2, acol = (tid & 3) * 4;
    const int brow = tid >> 5, bcol = (tid & 31) * 4;

    const float* agp = A + (size_t)(m0 + arow) * K + acol;
    const float* bgp = B + (size_t)brow * N + n0 + bcol;
    const uint32_t da0 = (uint32_t)__cvta_generic_to_shared(
        AsBase + (size_t)arow * A_STRIDE + acol);
    const uint32_t db0 = (uint32_t)__cvta_generic_to_shared(
        BsBase + (size_t)brow * B_STRIDE + bcol);

    float acc[2][8][4] = {};

    auto issue_stage = [&](int s, int k0) {
        uint32_t da = da0 + s * (A_STAGE_W * 4);
        const float* ap = agp + k0;
        CP_ASYNC16(da, ap);
        CP_ASYNC16(da + 64 * A_STRIDE * 4, ap + (size_t)64 * K);
        uint32_t db = db0 + s * (B_STAGE_W * 4);
        const float* bp = bgp + (size_t)k0 * N;
        CP_ASYNC16(db, bp);
        CP_ASYNC16(db + 8 * B_STRIDE * 4, bp + (size_t)8 * N);
    };

    auto mma_stage = [&](int s) {
        const uint32_t* As = AsBase + s * A_STAGE_W;
        const uint32_t* Bs = BsBase + s * B_STAGE_W;
#pragma unroll
        for (int kk = 0; kk < 16; kk += 8) {
            uint32_t af[2][4], bf[8][2];
#pragma unroll
            for (int mt = 0; mt < 2; mt++) {
                int mr = wm * 32 + mt * 16 + gid;
                const uint32_t* ar = As + mr * A_STRIDE + kk + tig;
                af[mt][0] = ar[0];
                af[mt][1] = ar[8 * A_STRIDE];
                af[mt][2] = ar[4];
                af[mt][3] = ar[8 * A_STRIDE + 4];
            }
#pragma unroll
            for (int nt = 0; nt < 8; nt++) {
                int nc = wn * 64 + nt * 8 + gid;
                const uint32_t* br = Bs + (kk + tig) * B_STRIDE + nc;
                bf[nt][0] = br[0];
                bf[nt][1] = br[4 * B_STRIDE];
            }
#pragma unroll
            for (int mt = 0; mt < 2; mt++)
#pragma unroll
                for (int nt = 0; nt < 8; nt++)
                    mma_tf32(acc[mt][nt], af[mt], bf[nt]);
        }
    };

    const int nk = K / 16;
#pragma unroll
    for (int s = 0; s < STAGES - 1; s++) {
        issue_stage(s, s * 16);
        CP_COMMIT();
    }
    for (int i = 0; i < nk; i++) {
        CP_WAIT2();
        __syncthreads();
        int kn = (i + STAGES - 1) * 16;
        if (kn < K) issue_stage((i + STAGES - 1) & (STAGES - 1), kn);
        CP_COMMIT();
        mma_stage(i & (STAGES - 1));
    }

#pragma unroll
    for (int mt = 0; mt < 2; mt++) {
        int r0 = m0 + wm * 32 + mt * 16 + gid;
#pragma unroll
        for (int nt = 0; nt < 8; nt++) {
            int col = n0 + wn * 64 + nt * 8 + tig * 2;
#pragma unroll
            for (int half = 0; half < 2; half++) {
                int row = r0 + half * 8;
                float v0 = acc[mt][nt][half * 2 + 0];
                float v1 = acc[mt][nt][half * 2 + 1];
                if (BIAS) { v0 += bias[col]; v1 += bias[col + 1]; }
                if (GELU_ACT) {
                    v0 = 0.5f * v0 * (1.0f + erff(v0 * 0.70710678118654752f));
                    v1 = 0.5f * v1 * (1.0f + erff(v1 * 0.70710678118654752f));
                }
                size_t idx = (size_t)row * N + col;
                if (NRES >= 1) { v0 += r1[idx]; v1 += r1[idx + 1]; }
                if (NRES >= 2) { v0 += r2[idx]; v1 += r2[idx + 1]; }
                *(float2*)&Cout[idx] = make_float2(v0, v1);
            }
        }
    }
}

// ---------------- fused flash attention on tf32 tensor cores ---------------
// One CTA per (64-query tile, b*h). 128 threads = 4 warps; warp owns 16 rows.
// Q pre-scaled by 0.125, A-fragments preloaded to regs. K smem stride 68,
// V stride 72 (both conflict-free for fragment LDS). P reuses the K buffer.
constexpr int QS_STRIDE = 68;
constexpr int VS_STRIDE = 72;
constexpr int ATTN_SMEM = (64 * QS_STRIDE * 2 + 64 * VS_STRIDE) * 4;  // 53248

__global__ __launch_bounds__(128) void attn_tc_kernel() {
    extern __shared__ float sm[];
    float* Qs = sm;                       // [64][68]
    float* Ps = sm + 64 * QS_STRIDE;      // K tile, then P   [64][68]
    float* Vs = sm + 2 * 64 * QS_STRIDE;  // [64][72]

    const int tid = threadIdx.x;
    const int bh = blockIdx.y, b = bh / NH, h = bh - b * NH;
    const int q0 = blockIdx.x * 64;
    const int warp = tid >> 5, lane = tid & 31;
    const int gid = lane >> 2, tig = lane & 3;
    const int r0 = warp * 16 + gid;       // first of this thread's row pair

    const float* qb = g_qkv + (size_t)b * SEQ * C3 + h * HD;
    const float* kb = qb + C;
    const float* vb = qb + 2 * C;

    // load Q tile, pre-scaled by 1/8
    {
        int row = tid >> 1, c0 = (tid & 1) * 32;
        const float* src = qb + (size_t)(q0 + row) * C3 + c0;
        float* dst = Qs + row * QS_STRIDE + c0;
#pragma unroll
        for (int c = 0; c < 8; c++) {
            float4 v = *(const float4*)(src + c * 4);
            dst[c * 4 + 0] = v.x * 0.125f; dst[c * 4 + 1] = v.y * 0.125f;
            dst[c * 4 + 2] = v.z * 0.125f; dst[c * 4 + 3] = v.w * 0.125f;
        }
    }
    __syncthreads();

    // preload Q A-fragments (8 k-steps x 4 regs)
    uint32_t qf[8][4];
    {
        const uint32_t* Q = (const uint32_t*)Qs;
#pragma unroll
        for (int kt = 0; kt < 8; kt++) {
            int kk = kt * 8;
            qf[kt][0] = Q[r0 * QS_STRIDE + kk + tig];
            qf[kt][1] = Q[(r0 + 8) * QS_STRIDE + kk + tig];
            qf[kt][2] = Q[r0 * QS_STRIDE + kk + tig + 4];
            qf[kt][3] = Q[(r0 + 8) * QS_STRIDE + kk + tig + 4];
        }
    }

    float acc_o[8][4] = {};
    float m0r = -1e30f, m1r = -1e30f, l0 = 0.f, l1 = 0.f;

    for (int kv0 = 0; kv0 < SEQ; kv0 += 64) {
        __syncthreads();   // prior iter done reading Ps/Vs
        {
            int row = tid >> 1, c0 = (tid & 1) * 32;
            const float* ks = kb + (size_t)(kv0 + row) * C3 + c0;
            const float* vs = vb + (size_t)(kv0 + row) * C3 + c0;
            float* kd = Ps + row * QS_STRIDE + c0;
            float* vd = Vs + row * VS_STRIDE + c0;
#pragma unroll
            for (int c = 0; c < 8; c++) {
                *(float4*)(kd + c * 4) = *(const float4*)(ks + c * 4);
                *(float4*)(vd + c * 4) = *(const float4*)(vs + c * 4);
            }
        }
        __syncthreads();

        // S = (Q/8) K^T
        float s[8][4] = {};
        {
            const uint32_t* Km = (const uint32_t*)Ps;
#pragma unroll
            for (int kt = 0; kt < 8; kt++) {
                int kk = kt * 8;
                uint32_t bf[8][2];
#pragma unroll
                for (int nt = 0; nt < 8; nt++) {
                    int n = nt * 8 + gid;
                    bf[nt][0] = Km[n * QS_STRIDE + kk + tig];
                    bf[nt][1] = Km[n * QS_STRIDE + kk + tig + 4];
                }
#pragma unroll
                for (int nt = 0; nt < 8; nt++)
                    mma_tf32(s[nt], qf[kt], bf[nt]);
            }
        }

        // online softmax (rows r0 and r0+8); reduce across the 4 tig lanes
        float mx0 = -1e30f, mx1 = -1e30f;
#pragma unroll
        for (int nt = 0; nt < 8; nt++) {
            mx0 = fmaxf(mx0, fmaxf(s[nt][0], s[nt][1]));
            mx1 = fmaxf(mx1, fmaxf(s[nt][2], s[nt][3]));
        }
        mx0 = fmaxf(mx0, __shfl_xor_sync(0xffffffffu, mx0, 1));
        mx0 = fmaxf(mx0, __shfl_xor_sync(0xffffffffu, mx0, 2));
        mx1 = fmaxf(mx1, __shfl_xor_sync(0xffffffffu, mx1, 1));
        mx1 = fmaxf(mx1, __shfl_xor_sync(0xffffffffu, mx1, 2));
        float mn0 = fmaxf(m0r, mx0), mn1 = fmaxf(m1r, mx1);
        float cr0 = __expf(m0r - mn0), cr1 = __expf(m1r - mn1);
        m0r = mn0; m1r = mn1;
        float sum0 = 0.f, sum1 = 0.f;
#pragma unroll
        for (int nt = 0; nt < 8; nt++) {
            s[nt][0] = __expf(s[nt][0] - mn0); sum0 += s[nt][0];
            s[nt][1] = __expf(s[nt][1] - mn0); sum0 += s[nt][1];
            s[nt][2] = __expf(s[nt][2] - mn1); sum1 += s[nt][2];
            s[nt][3] = __expf(s[nt][3] - mn1); sum1 += s[nt][3];
        }
        sum0 += __shfl_xor_sync(0xffffffffu, sum0, 1);
        sum0 += __shfl_xor_sync(0xffffffffu, sum0, 2);
        sum1 += __shfl_xor_sync(0xffffffffu, sum1, 1);
        sum1 += __shfl_xor_sync(0xffffffffu, sum1, 2);
        l0 = l0 * cr0 + sum0;
        l1 = l1 * cr1 + sum1;
#pragma unroll
        for (int nt = 0; nt < 8; nt++) {
            acc_o[nt][0] *= cr0; acc_o[nt][1] *= cr0;
            acc_o[nt][2] *= cr1; acc_o[nt][3] *= cr1;
        }

        __syncthreads();   // all warps done reading K tile
        // store P into the K buffer (warp-local rows)
#pragma unroll
        for (int nt = 0; nt < 8; nt++) {
            *(float2*)(Ps + r0 * QS_STRIDE + nt * 8 + 2 * tig) =
                make_float2(s[nt][0], s[nt][1]);
            *(float2*)(Ps + (r0 + 8) * QS_STRIDE + nt * 8 + 2 * tig) =
                make_float2(s[nt][2], s[nt][3]);
        }
        __syncwarp();

        // O += P @ V
        {
            const uint32_t* Pm = (const uint32_t*)Ps;
            const uint32_t* Vm = (const uint32_t*)Vs;
#pragma unroll
            for (int kt = 0; kt < 8; kt++) {
                int kk = kt * 8;
                uint32_t af[4];
                af[0] = Pm[r0 * QS_STRIDE + kk + tig];
                af[1] = Pm[(r0 + 8) * QS_STRIDE + kk + tig];
                af[2] = Pm[r0 * QS_STRIDE + kk + tig + 4];
                af[3] = Pm[(r0 + 8) * QS_STRIDE + kk + tig + 4];
                uint32_t bf[8][2];
#pragma unroll
                for (int nt = 0; nt < 8; nt++) {
                    int n = nt * 8 + gid;
                    bf[nt][0] = Vm[(kk + tig) * VS_STRIDE + n];
                    bf[nt][1] = Vm[(kk + tig + 4) * VS_STRIDE + n];
                }
#pragma unroll
                for (int nt = 0; nt < 8; nt++)
                    mma_tf32(acc_o[nt], af, bf[nt]);
            }
        }
    }

    // normalize + write [token, h*64 + d]
    float inv0 = 1.0f / l0, inv1 = 1.0f / l1;
    size_t row0 = (size_t)(b * SEQ + q0 + r0);
#pragma unroll
    for (int nt = 0; nt < 8; nt++) {
        int col = h * HD + nt * 8 + 2 * tig;
        *(float2*)&g_attn[row0 * C + col] =
            make_float2(acc_o[nt][0] * inv0, acc_o[nt][1] * inv0);
        *(float2*)&g_attn[(row0 + 8) * C + col] =
            make_float2(acc_o[nt][2] * inv1, acc_o[nt][3] * inv1);
    }
}

// ---------------- launch ---------------------------------------------------
extern "C" void kernel_launch(void* const* d_in, const int* in_sizes, int n_in,
                              void* d_out, int out_size) {
    const float* x    = (const float*)d_in[0];
    const float* ln1g = (const float*)d_in[1];
    const float* ln1b = (const float*)d_in[2];
    const float* wqkv = (const float*)d_in[3];
    const float* wout = (const float*)d_in[4];
    const float* bout = (const float*)d_in[5];
    const float* ln2g = (const float*)d_in[6];
    const float* ln2b = (const float*)d_in[7];
    const float* w1   = (const float*)d_in[8];
    const float* b1   = (const float*)d_in[9];
    const float* w2   = (const float*)d_in[10];
    const float* b2   = (const float*)d_in[11];
    float* out = (float*)d_out;

    float *h1, *qkvp, *attnp, *x1p, *h2p, *midp;
    cudaGetSymbolAddress((void**)&h1,    g_h1);
    cudaGetSymbolAddress((void**)&qkvp,  g_qkv);
    cudaGetSymbolAddress((void**)&attnp, g_attn);
    cudaGetSymbolAddress((void**)&x1p,   g_x1);
    cudaGetSymbolAddress((void**)&h2p,   g_h2);
    cudaGetSymbolAddress((void**)&midp,  g_mid);

    cudaFuncSetAttribute(attn_tc_kernel, cudaFuncAttributeMaxDynamicSharedMemorySize,
                         ATTN_SMEM);
    cudaFuncSetAttribute(gemm_tc<false, false, 0>,
                         cudaFuncAttributeMaxDynamicSharedMemorySize, GEMM_SMEM);
    cudaFuncSetAttribute(gemm_tc<true, false, 2>,
                         cudaFuncAttributeMaxDynamicSharedMemorySize, GEMM_SMEM);
    cudaFuncSetAttribute(gemm_tc<true, true, 0>,
                         cudaFuncAttributeMaxDynamicSharedMemorySize, GEMM_SMEM);
    cudaFuncSetAttribute(gemm_tc<true, false, 1>,
                         cudaFuncAttributeMaxDynamicSharedMemorySize, GEMM_SMEM);

    // 1) h = LN1(x)
    ln_kernel<<<TOK, 256>>>(x, ln1g, ln1b, h1);
    // 2) qkv = h @ w_qkv
    gemm_tc<false, false, 0><<<dim3(C3 / 128, TOK / 128), 256, GEMM_SMEM>>>(
        h1, wqkv, nullptr, nullptr, nullptr, qkvp, C3, C);
    // 3) fused attention: softmax(QK^T/8) @ V   (tf32 tensor cores)
    attn_tc_kernel<<<dim3(SEQ / 64, BH), 128, ATTN_SMEM>>>();
    // 4) x1 = x + h + attn @ w_out + b_out   (double residual)
    gemm_tc<true, false, 2><<<dim3(C / 128, TOK / 128), 256, GEMM_SMEM>>>(
        attnp, wout, bout, x, h1, x1p, C, C);
    // 5) h2 = LN2(x1)
    ln_kernel<<<TOK, 256>>>(x1p, ln2g, ln2b, h2p);
    // 6) mid = gelu(h2 @ w1 + b1)
    gemm_tc<true, true, 0><<<dim3(MD / 128, TOK / 128), 256, GEMM_SMEM>>>(
        h2p, w1, b1, nullptr, nullptr, midp, MD, C);
    // 7) out = x1 + mid @ w2 + b2
    gemm_tc<true, false, 1><<<dim3(C / 128, TOK / 128), 256, GEMM_SMEM>>>(
        midp, w2, b2, x1p, nullptr, out, C, MD);
}

// round 13
// speedup vs baseline: 1.7777x; 1.2495x over previous
#include <cuda_runtime.h>
#include <cuda_fp16.h>
#include <math.h>
#include <stdint.h>

constexpr int TOK = 4096;   // B*N tokens
constexpr int C   = 768;
constexpr int C3  = 2304;
constexpr int MD  = 3072;
constexpr int NH  = 12;
constexpr int HD  = 64;
constexpr int SEQ = 1024;
constexpr int BH  = 48;     // B*NH

// ---------------- scratch (device globals; no allocation allowed) ----------
__device__ __half g_h1h[TOK * C];      // LN1 out (half, GEMM A + residual)
__device__ float  g_qkv[TOK * C3];     // qkv (fp32, attention reads)
__device__ __half g_attnh[TOK * C];    // attention out (half, GEMM A)
__device__ float  g_x1[TOK * C];       // post-attn residual (fp32)
__device__ __half g_h2h[TOK * C];      // LN2 out (half)
__device__ __half g_midh[TOK * MD];    // gelu out (half)
// transposed+converted weights, half [N][K]
__device__ __half g_wtqkv[C3 * C];
__device__ __half g_wtout[C * C];
__device__ __half g_wt1[MD * C];
__device__ __half g_wt2[C * MD];

#define CP_ASYNC16(dst, src) \
    asm volatile("cp.async.cg.shared.global [%0], [%1], 16;\n" :: "r"(dst), "l"(src))
#define CP_COMMIT() asm volatile("cp.async.commit_group;\n" ::)
#define CP_WAIT2()  asm volatile("cp.async.wait_group 2;\n" ::)

__device__ __forceinline__ void mma_f16(float* d, const uint32_t* a, const uint32_t* b) {
    asm volatile(
        "mma.sync.aligned.m16n8k16.row.col.f32.f16.f16.f32 "
        "{%0,%1,%2,%3}, {%4,%5,%6,%7}, {%8,%9}, {%0,%1,%2,%3};"
        : "+f"(d[0]), "+f"(d[1]), "+f"(d[2]), "+f"(d[3])
        : "r"(a[0]), "r"(a[1]), "r"(a[2]), "r"(a[3]), "r"(b[0]), "r"(b[1]));
}
__device__ __forceinline__ void mma_tf32(float* d, const uint32_t* a, const uint32_t* b) {
    asm volatile(
        "mma.sync.aligned.m16n8k8.row.col.f32.tf32.tf32.f32 "
        "{%0,%1,%2,%3}, {%4,%5,%6,%7}, {%8,%9}, {%0,%1,%2,%3};"
        : "+f"(d[0]), "+f"(d[1]), "+f"(d[2]), "+f"(d[3])
        : "r"(a[0]), "r"(a[1]), "r"(a[2]), "r"(a[3]), "r"(b[0]), "r"(b[1]));
}

// ---------------- weight transpose+convert: out[n][k] = (half)in[k][n] -----
__global__ void transpose_cvt_kernel(const float* __restrict__ in,
                                     __half* __restrict__ out, int K, int N) {
    __shared__ float t[32][33];
    int n = blockIdx.x * 32 + threadIdx.x;
    int k0 = blockIdx.y * 32;
    for (int j = threadIdx.y; j < 32; j += 8)
        t[j][threadIdx.x] = in[(size_t)(k0 + j) * N + n];
    __syncthreads();
    int k = k0 + threadIdx.x;
    int nn0 = blockIdx.x * 32;
    for (int j = threadIdx.y; j < 32; j += 8)
        out[(size_t)(nn0 + j) * K + k] = __float2half_rn(t[threadIdx.x][j]);
}

// ---------------- LayerNorm: fp32 math, half output ------------------------
__global__ void ln_kernel(const float* __restrict__ x, const float* __restrict__ g,
                          const float* __restrict__ b, __half* __restrict__ out) {
    __shared__ float s1[256], s2[256];
    int row = blockIdx.x, t = threadIdx.x;
    const float* xr = x + (size_t)row * C;
    float v0 = xr[t], v1 = xr[t + 256], v2 = xr[t + 512];
    s1[t] = v0 + v1 + v2;
    s2[t] = v0 * v0 + v1 * v1 + v2 * v2;
    __syncthreads();
    for (int o = 128; o > 0; o >>= 1) {
        if (t < o) { s1[t] += s1[t + o]; s2[t] += s2[t + o]; }
        __syncthreads();
    }
    float mean = s1[0] * (1.0f / C);
    float var  = s2[0] * (1.0f / C) - mean * mean;
    float inv  = rsqrtf(var + 1e-5f);
    __half* orow = out + (size_t)row * C;
    orow[t]       = __float2half_rn((v0 - mean) * inv * g[t]       + b[t]);
    orow[t + 256] = __float2half_rn((v1 - mean) * inv * g[t + 256] + b[t + 256]);
    orow[t + 512] = __float2half_rn((v2 - mean) * inv * g[t + 512] + b[t + 512]);
}

// ---------------- FP16 tensor-core GEMM, cp.async 4-stage ------------------
// 128x128 CTA tile, BK=32 (half), 256 threads = 8 warps (4 M x 2 N),
// warp tile 32x64, mma.m16n8k16 f16 with fp32 accum.
// A[m][k], Bt[n][k] half tiles: rows of 32 half (64 B) padded to 80 B
// (20 words: bank = (20r + tig) mod 32 -> all 32 lanes distinct).
constexpr int STAGES = 4;
constexpr int ROW_W = 20;                       // 32-bit words per smem row
constexpr int STAGE_W = 128 * ROW_W;            // words per A (or B) stage
constexpr int GEMM_SMEM = STAGES * 2 * STAGE_W * 4;   // 81920 B

template <bool BIAS, bool GELU_ACT, int NRES, bool HALF_OUT>
__global__ __launch_bounds__(256, 2) void gemm_h(
    const __half* __restrict__ A, const __half* __restrict__ Bt,
    const float* __restrict__ bias, const float* __restrict__ r1,
    const __half* __restrict__ r2, void* __restrict__ CoutV, int N, int K) {
    extern __shared__ uint32_t smem[];
    uint32_t* AsBase = smem;                       // [STAGES][128][20]
    uint32_t* BsBase = smem + STAGES * STAGE_W;    // [STAGES][128][20]

    const int tid = threadIdx.x;
    const int m0 = blockIdx.y * 128, n0 = blockIdx.x * 128;
    const int warp = tid >> 5, lane = tid & 31;
    const int wm = warp & 3, wn = warp >> 2;
    const int gid = lane >> 2, tig = lane & 3;

    const int lrow = tid >> 1;                  // 0..127
    const int lseg = (tid & 1) * 16;            // halfword offset 0/16

    const __half* ag = A  + (size_t)(m0 + lrow) * K + lseg;
    const __half* bg = Bt + (size_t)(n0 + lrow) * K + lseg;
    const uint32_t da0 = (uint32_t)__cvta_generic_to_shared(AsBase) + lrow * 80 + lseg * 2;
    const uint32_t db0 = (uint32_t)__cvta_generic_to_shared(BsBase) + lrow * 80 + lseg * 2;

    float acc[2][8][4] = {};

    auto issue_stage = [&](int s, int k0) {
        uint32_t da = da0 + s * (STAGE_W * 4);
        const __half* ap = ag + k0;
        CP_ASYNC16(da, ap);
        CP_ASYNC16(da + 16, ap + 8);
        uint32_t db = db0 + s * (STAGE_W * 4);
        const __half* bp = bg + k0;
        CP_ASYNC16(db, bp);
        CP_ASYNC16(db + 16, bp + 8);
    };

    auto mma_stage = [&](int s) {
        const uint32_t* As = AsBase + s * STAGE_W;
        const uint32_t* Bs = BsBase + s * STAGE_W;
#pragma unroll
        for (int kc2 = 0; kc2 < 16; kc2 += 8) {   // k16 step, in word units
            uint32_t af[2][4], bf[8][2];
#pragma unroll
            for (int mt = 0; mt < 2; mt++) {
                int mr = wm * 32 + mt * 16 + gid;
                const uint32_t* ar = As + mr * ROW_W + kc2 + tig;
                af[mt][0] = ar[0];
                af[mt][1] = ar[8 * ROW_W];
                af[mt][2] = ar[4];
                af[mt][3] = ar[8 * ROW_W + 4];
            }
#pragma unroll
            for (int nt = 0; nt < 8; nt++) {
                int nc = wn * 64 + nt * 8 + gid;
                const uint32_t* br = Bs + nc * ROW_W + kc2 + tig;
                bf[nt][0] = br[0];
                bf[nt][1] = br[4];
            }
#pragma unroll
            for (int mt = 0; mt < 2; mt++)
#pragma unroll
                for (int nt = 0; nt < 8; nt++)
                    mma_f16(acc[mt][nt], af[mt], bf[nt]);
        }
    };

    const int nk = K / 32;
#pragma unroll
    for (int s = 0; s < STAGES - 1; s++) {
        issue_stage(s, s * 32);
        CP_COMMIT();
    }
    for (int i = 0; i < nk; i++) {
        CP_WAIT2();
        __syncthreads();
        int kn = (i + STAGES - 1) * 32;
        if (kn < K) issue_stage((i + STAGES - 1) & (STAGES - 1), kn);
        CP_COMMIT();
        mma_stage(i & (STAGES - 1));
    }

    // epilogue
#pragma unroll
    for (int mt = 0; mt < 2; mt++) {
        int r0 = m0 + wm * 32 + mt * 16 + gid;
#pragma unroll
        for (int nt = 0; nt < 8; nt++) {
            int col = n0 + wn * 64 + nt * 8 + tig * 2;
#pragma unroll
            for (int half_i = 0; half_i < 2; half_i++) {
                int row = r0 + half_i * 8;
                float v0 = acc[mt][nt][half_i * 2 + 0];
                float v1 = acc[mt][nt][half_i * 2 + 1];
                if (BIAS) { v0 += bias[col]; v1 += bias[col + 1]; }
                if (GELU_ACT) {
                    v0 = 0.5f * v0 * (1.0f + erff(v0 * 0.70710678118654752f));
                    v1 = 0.5f * v1 * (1.0f + erff(v1 * 0.70710678118654752f));
                }
                size_t idx = (size_t)row * N + col;
                if (NRES >= 1) { v0 += r1[idx]; v1 += r1[idx + 1]; }
                if (NRES >= 2) {
                    v0 += __half2float(r2[idx]);
                    v1 += __half2float(r2[idx + 1]);
                }
                if (HALF_OUT) {
                    *(__half2*)&((__half*)CoutV)[idx] = __floats2half2_rn(v0, v1);
                } else {
                    *(float2*)&((float*)CoutV)[idx] = make_float2(v0, v1);
                }
            }
        }
    }
}

// ---------------- fused flash attention on tf32 mma.sync (round-8) ---------
// reads fp32 g_qkv; writes half g_attnh
constexpr int QS_STRIDE = 68;
constexpr int VS_STRIDE = 72;
constexpr int ATTN_SMEM = (64 * QS_STRIDE * 2 + 64 * VS_STRIDE) * 4;  // 53248

__global__ __launch_bounds__(128) void attn_tc_kernel() {
    extern __shared__ float sm[];
    float* Qs = sm;
    float* Ps = sm + 64 * QS_STRIDE;
    float* Vs = sm + 2 * 64 * QS_STRIDE;

    const int tid = threadIdx.x;
    const int bh = blockIdx.y, b = bh / NH, h = bh - b * NH;
    const int q0 = blockIdx.x * 64;
    const int warp = tid >> 5, lane = tid & 31;
    const int gid = lane >> 2, tig = lane & 3;
    const int r0 = warp * 16 + gid;

    const float* qb = g_qkv + (size_t)b * SEQ * C3 + h * HD;
    const float* kb = qb + C;
    const float* vb = qb + 2 * C;

    {
        int row = tid >> 1, c0 = (tid & 1) * 32;
        const float* src = qb + (size_t)(q0 + row) * C3 + c0;
        float* dst = Qs + row * QS_STRIDE + c0;
#pragma unroll
        for (int c = 0; c < 8; c++) {
            float4 v = *(const float4*)(src + c * 4);
            dst[c * 4 + 0] = v.x * 0.125f; dst[c * 4 + 1] = v.y * 0.125f;
            dst[c * 4 + 2] = v.z * 0.125f; dst[c * 4 + 3] = v.w * 0.125f;
        }
    }
    __syncthreads();

    uint32_t qf[8][4];
    {
        const uint32_t* Q = (const uint32_t*)Qs;
#pragma unroll
        for (int kt = 0; kt < 8; kt++) {
            int kk = kt * 8;
            qf[kt][0] = Q[r0 * QS_STRIDE + kk + tig];
            qf[kt][1] = Q[(r0 + 8) * QS_STRIDE + kk + tig];
            qf[kt][2] = Q[r0 * QS_STRIDE + kk + tig + 4];
            qf[kt][3] = Q[(r0 + 8) * QS_STRIDE + kk + tig + 4];
        }
    }

    float acc_o[8][4] = {};
    float m0r = -1e30f, m1r = -1e30f, l0 = 0.f, l1 = 0.f;

    for (int kv0 = 0; kv0 < SEQ; kv0 += 64) {
        __syncthreads();
        {
            int row = tid >> 1, c0 = (tid & 1) * 32;
            const float* ks = kb + (size_t)(kv0 + row) * C3 + c0;
            const float* vs = vb + (size_t)(kv0 + row) * C3 + c0;
            float* kd = Ps + row * QS_STRIDE + c0;
            float* vd = Vs + row * VS_STRIDE + c0;
#pragma unroll
            for (int c = 0; c < 8; c++) {
                *(float4*)(kd + c * 4) = *(const float4*)(ks + c * 4);
                *(float4*)(vd + c * 4) = *(const float4*)(vs + c * 4);
            }
        }
        __syncthreads();

        float s[8][4] = {};
        {
            const uint32_t* Km = (const uint32_t*)Ps;
#pragma unroll
            for (int kt = 0; kt < 8; kt++) {
                int kk = kt * 8;
                uint32_t bf[8][2];
#pragma unroll
                for (int nt = 0; nt < 8; nt++) {
                    int n = nt * 8 + gid;
                    bf[nt][0] = Km[n * QS_STRIDE + kk + tig];
                    bf[nt][1] = Km[n * QS_STRIDE + kk + tig + 4];
                }
#pragma unroll
                for (int nt = 0; nt < 8; nt++)
                    mma_tf32(s[nt], qf[kt], bf[nt]);
            }
        }

        float mx0 = -1e30f, mx1 = -1e30f;
#pragma unroll
        for (int nt = 0; nt < 8; nt++) {
            mx0 = fmaxf(mx0, fmaxf(s[nt][0], s[nt][1]));
            mx1 = fmaxf(mx1, fmaxf(s[nt][2], s[nt][3]));
        }
        mx0 = fmaxf(mx0, __shfl_xor_sync(0xffffffffu, mx0, 1));
        mx0 = fmaxf(mx0, __shfl_xor_sync(0xffffffffu, mx0, 2));
        mx1 = fmaxf(mx1, __shfl_xor_sync(0xffffffffu, mx1, 1));
        mx1 = fmaxf(mx1, __shfl_xor_sync(0xffffffffu, mx1, 2));
        float mn0 = fmaxf(m0r, mx0), mn1 = fmaxf(m1r, mx1);
        float cr0 = __expf(m0r - mn0), cr1 = __expf(m1r - mn1);
        m0r = mn0; m1r = mn1;
        float sum0 = 0.f, sum1 = 0.f;
#pragma unroll
        for (int nt = 0; nt < 8; nt++) {
            s[nt][0] = __expf(s[nt][0] - mn0); sum0 += s[nt][0];
            s[nt][1] = __expf(s[nt][1] - mn0); sum0 += s[nt][1];
            s[nt][2] = __expf(s[nt][2] - mn1); sum1 += s[nt][2];
            s[nt][3] = __expf(s[nt][3] - mn1); sum1 += s[nt][3];
        }
        sum0 += __shfl_xor_sync(0xffffffffu, sum0, 1);
        sum0 += __shfl_xor_sync(0xffffffffu, sum0, 2);
        sum1 += __shfl_xor_sync(0xffffffffu, sum1, 1);
        sum1 += __shfl_xor_sync(0xffffffffu, sum1, 2);
        l0 = l0 * cr0 + sum0;
        l1 = l1 * cr1 + sum1;
#pragma unroll
        for (int nt = 0; nt < 8; nt++) {
            acc_o[nt][0] *= cr0; acc_o[nt][1] *= cr0;
            acc_o[nt][2] *= cr1; acc_o[nt][3] *= cr1;
        }

        __syncthreads();
#pragma unroll
        for (int nt = 0; nt < 8; nt++) {
            *(float2*)(Ps + r0 * QS_STRIDE + nt * 8 + 2 * tig) =
                make_float2(s[nt][0], s[nt][1]);
            *(float2*)(Ps + (r0 + 8) * QS_STRIDE + nt * 8 + 2 * tig) =
                make_float2(s[nt][2], s[nt][3]);
        }
        __syncwarp();

        {
            const uint32_t* Pm = (const uint32_t*)Ps;
            const uint32_t* Vm = (const uint32_t*)Vs;
#pragma unroll
            for (int kt = 0; kt < 8; kt++) {
                int kk = kt * 8;
                uint32_t af[4];
                af[0] = Pm[r0 * QS_STRIDE + kk + tig];
                af[1] = Pm[(r0 + 8) * QS_STRIDE + kk + tig];
                af[2] = Pm[r0 * QS_STRIDE + kk + tig + 4];
                af[3] = Pm[(r0 + 8) * QS_STRIDE + kk + tig + 4];
                uint32_t bf[8][2];
#pragma unroll
                for (int nt = 0; nt < 8; nt++) {
                    int n = nt * 8 + gid;
                    bf[nt][0] = Vm[(kk + tig) * VS_STRIDE + n];
                    bf[nt][1] = Vm[(kk + tig + 4) * VS_STRIDE + n];
                }
#pragma unroll
                for (int nt = 0; nt < 8; nt++)
                    mma_tf32(acc_o[nt], af, bf[nt]);
            }
        }
    }

    float inv0 = 1.0f / l0, inv1 = 1.0f / l1;
    size_t row0 = (size_t)(b * SEQ + q0 + r0);
#pragma unroll
    for (int nt = 0; nt < 8; nt++) {
        int col = h * HD + nt * 8 + 2 * tig;
        *(__half2*)&g_attnh[row0 * C + col] =
            __floats2half2_rn(acc_o[nt][0] * inv0, acc_o[nt][1] * inv0);
        *(__half2*)&g_attnh[(row0 + 8) * C + col] =
            __floats2half2_rn(acc_o[nt][2] * inv1, acc_o[nt][3] * inv1);
    }
}

// ---------------- launch ---------------------------------------------------
extern "C" void kernel_launch(void* const* d_in, const int* in_sizes, int n_in,
                              void* d_out, int out_size) {
    const float* x    = (const float*)d_in[0];
    const float* ln1g = (const float*)d_in[1];
    const float* ln1b = (const float*)d_in[2];
    const float* wqkv = (const float*)d_in[3];
    const float* wout = (const float*)d_in[4];
    const float* bout = (const float*)d_in[5];
    const float* ln2g = (const float*)d_in[6];
    const float* ln2b = (const float*)d_in[7];
    const float* w1   = (const float*)d_in[8];
    const float* b1   = (const float*)d_in[9];
    const float* w2   = (const float*)d_in[10];
    const float* b2   = (const float*)d_in[11];
    float* out = (float*)d_out;

    __half *h1h, *attnh, *h2h, *midh, *wtqkv, *wtout, *wt1, *wt2;
    float *qkvp, *x1p;
    cudaGetSymbolAddress((void**)&h1h,   g_h1h);
    cudaGetSymbolAddress((void**)&qkvp,  g_qkv);
    cudaGetSymbolAddress((void**)&attnh, g_attnh);
    cudaGetSymbolAddress((void**)&x1p,   g_x1);
    cudaGetSymbolAddress((void**)&h2h,   g_h2h);
    cudaGetSymbolAddress((void**)&midh,  g_midh);
    cudaGetSymbolAddress((void**)&wtqkv, g_wtqkv);
    cudaGetSymbolAddress((void**)&wtout, g_wtout);
    cudaGetSymbolAddress((void**)&wt1,   g_wt1);
    cudaGetSymbolAddress((void**)&wt2,   g_wt2);

    cudaFuncSetAttribute(attn_tc_kernel, cudaFuncAttributeMaxDynamicSharedMemorySize,
                         ATTN_SMEM);
    cudaFuncSetAttribute(gemm_h<false, false, 0, false>,
                         cudaFuncAttributeMaxDynamicSharedMemorySize, GEMM_SMEM);
    cudaFuncSetAttribute(gemm_h<true, false, 2, false>,
                         cudaFuncAttributeMaxDynamicSharedMemorySize, GEMM_SMEM);
    cudaFuncSetAttribute(gemm_h<true, true, 0, true>,
                         cudaFuncAttributeMaxDynamicSharedMemorySize, GEMM_SMEM);
    cudaFuncSetAttribute(gemm_h<true, false, 1, false>,
                         cudaFuncAttributeMaxDynamicSharedMemorySize, GEMM_SMEM);

    dim3 tb(32, 8);
    // 0) transpose+convert weights to half [N][K]
    transpose_cvt_kernel<<<dim3(C3 / 32, C / 32), tb>>>(wqkv, wtqkv, C, C3);
    transpose_cvt_kernel<<<dim3(C / 32, C / 32), tb>>>(wout, wtout, C, C);
    transpose_cvt_kernel<<<dim3(MD / 32, C / 32), tb>>>(w1, wt1, C, MD);
    transpose_cvt_kernel<<<dim3(C / 32, MD / 32), tb>>>(w2, wt2, MD, C);
    // 1) h = LN1(x)  (half out)
    ln_kernel<<<TOK, 256>>>(x, ln1g, ln1b, h1h);
    // 2) qkv = h @ w_qkv  (fp32 out)
    gemm_h<false, false, 0, false><<<dim3(C3 / 128, TOK / 128), 256, GEMM_SMEM>>>(
        h1h, wtqkv, nullptr, nullptr, nullptr, qkvp, C3, C);
    // 3) fused attention (tf32; half out)
    attn_tc_kernel<<<dim3(SEQ / 64, BH), 128, ATTN_SMEM>>>();
    // 4) x1 = x + h + attn @ w_out + b_out
    gemm_h<true, false, 2, false><<<dim3(C / 128, TOK / 128), 256, GEMM_SMEM>>>(
        attnh, wtout, bout, x, h1h, x1p, C, C);
    // 5) h2 = LN2(x1)  (half out)
    ln_kernel<<<TOK, 256>>>(x1p, ln2g, ln2b, h2h);
    // 6) mid = gelu(h2 @ w1 + b1)  (half out)
    gemm_h<true, true, 0, true><<<dim3(MD / 128, TOK / 128), 256, GEMM_SMEM>>>(
        h2h, wt1, b1, nullptr, nullptr, midh, MD, C);
    // 7) out = x1 + mid @ w2 + b2
    gemm_h<true, false, 1, false><<<dim3(C / 128, TOK / 128), 256, GEMM_SMEM>>>(
        midh, wt2, b2, x1p, nullptr, out, C, MD);
}

// round 14
// speedup vs baseline: 2.2912x; 1.2889x over previous
#include <cuda_runtime.h>
#include <cuda_fp16.h>
#include <math.h>
#include <stdint.h>

constexpr int TOK = 4096;   // B*N tokens
constexpr int C   = 768;
constexpr int C3  = 2304;
constexpr int MD  = 3072;
constexpr int NH  = 12;
constexpr int HD  = 64;
constexpr int SEQ = 1024;
constexpr int BH  = 48;     // B*NH

// ---------------- scratch (device globals; no allocation allowed) ----------
__device__ __half g_h1h[TOK * C];      // LN1 out (half)
__device__ __half g_qkvh[TOK * C3];    // qkv (half)
__device__ __half g_vth[BH * HD * SEQ];// V transposed per head: [bh][d][kv]
__device__ __half g_attnh[TOK * C];    // attention out (half)
__device__ float  g_x1[TOK * C];       // post-attn residual (fp32)
__device__ __half g_h2h[TOK * C];      // LN2 out (half)
__device__ __half g_midh[TOK * MD];    // gelu out (half)
// transposed+converted weights, half [N][K]
__device__ __half g_wtqkv[C3 * C];
__device__ __half g_wtout[C * C];
__device__ __half g_wt1[MD * C];
__device__ __half g_wt2[C * MD];

#define CP_ASYNC16(dst, src) \
    asm volatile("cp.async.cg.shared.global [%0], [%1], 16;\n" :: "r"(dst), "l"(src))
#define CP_COMMIT() asm volatile("cp.async.commit_group;\n" ::)
#define CP_WAIT2()  asm volatile("cp.async.wait_group 2;\n" ::)

__device__ __forceinline__ void mma_f16(float* d, const uint32_t* a, const uint32_t* b) {
    asm volatile(
        "mma.sync.aligned.m16n8k16.row.col.f32.f16.f16.f32 "
        "{%0,%1,%2,%3}, {%4,%5,%6,%7}, {%8,%9}, {%0,%1,%2,%3};"
        : "+f"(d[0]), "+f"(d[1]), "+f"(d[2]), "+f"(d[3])
        : "r"(a[0]), "r"(a[1]), "r"(a[2]), "r"(a[3]), "r"(b[0]), "r"(b[1]));
}

// ---------------- weight transpose+convert: out[n][k] = (half)in[k][n] -----
__global__ void transpose_cvt_kernel(const float* __restrict__ in,
                                     __half* __restrict__ out, int K, int N) {
    __shared__ float t[32][33];
    int n = blockIdx.x * 32 + threadIdx.x;
    int k0 = blockIdx.y * 32;
    for (int j = threadIdx.y; j < 32; j += 8)
        t[j][threadIdx.x] = in[(size_t)(k0 + j) * N + n];
    __syncthreads();
    int k = k0 + threadIdx.x;
    int nn0 = blockIdx.x * 32;
    for (int j = threadIdx.y; j < 32; j += 8)
        out[(size_t)(nn0 + j) * K + k] = __float2half_rn(t[threadIdx.x][j]);
}

// ---------------- V transpose: g_qkvh V-part -> g_vth[bh][d][kv] -----------
__global__ void vt_kernel() {
    __shared__ __half t[32][33];
    int bh = blockIdx.z, b = bh / NH, h = bh - b * NH;
    int kv0 = blockIdx.y * 32, d0 = blockIdx.x * 32;
    int tx = threadIdx.x, ty = threadIdx.y;
    for (int j = ty; j < 32; j += 8)
        t[j][tx] = g_qkvh[(size_t)(b * SEQ + kv0 + j) * C3 + 2 * C + h * HD + d0 + tx];
    __syncthreads();
    for (int j = ty; j < 32; j += 8)
        g_vth[(size_t)bh * HD * SEQ + (size_t)(d0 + j) * SEQ + kv0 + tx] = t[tx][j];
}

// ---------------- LayerNorm: fp32 math, half output ------------------------
__global__ void ln_kernel(const float* __restrict__ x, const float* __restrict__ g,
                          const float* __restrict__ b, __half* __restrict__ out) {
    __shared__ float s1[256], s2[256];
    int row = blockIdx.x, t = threadIdx.x;
    const float* xr = x + (size_t)row * C;
    float v0 = xr[t], v1 = xr[t + 256], v2 = xr[t + 512];
    s1[t] = v0 + v1 + v2;
    s2[t] = v0 * v0 + v1 * v1 + v2 * v2;
    __syncthreads();
    for (int o = 128; o > 0; o >>= 1) {
        if (t < o) { s1[t] += s1[t + o]; s2[t] += s2[t + o]; }
        __syncthreads();
    }
    float mean = s1[0] * (1.0f / C);
    float var  = s2[0] * (1.0f / C) - mean * mean;
    float inv  = rsqrtf(var + 1e-5f);
    __half* orow = out + (size_t)row * C;
    orow[t]       = __float2half_rn((v0 - mean) * inv * g[t]       + b[t]);
    orow[t + 256] = __float2half_rn((v1 - mean) * inv * g[t + 256] + b[t + 256]);
    orow[t + 512] = __float2half_rn((v2 - mean) * inv * g[t + 512] + b[t + 512]);
}

// ---------------- FP16 tensor-core GEMM, cp.async 4-stage (round-13) -------
constexpr int STAGES = 4;
constexpr int ROW_W = 20;
constexpr int STAGE_W = 128 * ROW_W;
constexpr int GEMM_SMEM = STAGES * 2 * STAGE_W * 4;   // 81920 B

template <bool BIAS, bool GELU_ACT, int NRES, bool HALF_OUT>
__global__ __launch_bounds__(256, 2) void gemm_h(
    const __half* __restrict__ A, const __half* __restrict__ Bt,
    const float* __restrict__ bias, const float* __restrict__ r1,
    const __half* __restrict__ r2, void* __restrict__ CoutV, int N, int K) {
    extern __shared__ uint32_t smem[];
    uint32_t* AsBase = smem;
    uint32_t* BsBase = smem + STAGES * STAGE_W;

    const int tid = threadIdx.x;
    const int m0 = blockIdx.y * 128, n0 = blockIdx.x * 128;
    const int warp = tid >> 5, lane = tid & 31;
    const int wm = warp & 3, wn = warp >> 2;
    const int gid = lane >> 2, tig = lane & 3;

    const int lrow = tid >> 1;
    const int lseg = (tid & 1) * 16;

    const __half* ag = A  + (size_t)(m0 + lrow) * K + lseg;
    const __half* bg = Bt + (size_t)(n0 + lrow) * K + lseg;
    const uint32_t da0 = (uint32_t)__cvta_generic_to_shared(AsBase) + lrow * 80 + lseg * 2;
    const uint32_t db0 = (uint32_t)__cvta_generic_to_shared(BsBase) + lrow * 80 + lseg * 2;

    float acc[2][8][4] = {};

    auto issue_stage = [&](int s, int k0) {
        uint32_t da = da0 + s * (STAGE_W * 4);
        const __half* ap = ag + k0;
        CP_ASYNC16(da, ap);
        CP_ASYNC16(da + 16, ap + 8);
        uint32_t db = db0 + s * (STAGE_W * 4);
        const __half* bp = bg + k0;
        CP_ASYNC16(db, bp);
        CP_ASYNC16(db + 16, bp + 8);
    };

    auto mma_stage = [&](int s) {
        const uint32_t* As = AsBase + s * STAGE_W;
        const uint32_t* Bs = BsBase + s * STAGE_W;
#pragma unroll
        for (int kc2 = 0; kc2 < 16; kc2 += 8) {
            uint32_t af[2][4], bf[8][2];
#pragma unroll
            for (int mt = 0; mt < 2; mt++) {
                int mr = wm * 32 + mt * 16 + gid;
                const uint32_t* ar = As + mr * ROW_W + kc2 + tig;
                af[mt][0] = ar[0];
                af[mt][1] = ar[8 * ROW_W];
                af[mt][2] = ar[4];
                af[mt][3] = ar[8 * ROW_W + 4];
            }
#pragma unroll
            for (int nt = 0; nt < 8; nt++) {
                int nc = wn * 64 + nt * 8 + gid;
                const uint32_t* br = Bs + nc * ROW_W + kc2 + tig;
                bf[nt][0] = br[0];
                bf[nt][1] = br[4];
            }
#pragma unroll
            for (int mt = 0; mt < 2; mt++)
#pragma unroll
                for (int nt = 0; nt < 8; nt++)
                    mma_f16(acc[mt][nt], af[mt], bf[nt]);
        }
    };

    const int nk = K / 32;
#pragma unroll
    for (int s = 0; s < STAGES - 1; s++) {
        issue_stage(s, s * 32);
        CP_COMMIT();
    }
    for (int i = 0; i < nk; i++) {
        CP_WAIT2();
        __syncthreads();
        int kn = (i + STAGES - 1) * 32;
        if (kn < K) issue_stage((i + STAGES - 1) & (STAGES - 1), kn);
        CP_COMMIT();
        mma_stage(i & (STAGES - 1));
    }

#pragma unroll
    for (int mt = 0; mt < 2; mt++) {
        int r0 = m0 + wm * 32 + mt * 16 + gid;
#pragma unroll
        for (int nt = 0; nt < 8; nt++) {
            int col = n0 + wn * 64 + nt * 8 + tig * 2;
#pragma unroll
            for (int half_i = 0; half_i < 2; half_i++) {
                int row = r0 + half_i * 8;
                float v0 = acc[mt][nt][half_i * 2 + 0];
                float v1 = acc[mt][nt][half_i * 2 + 1];
                if (BIAS) { v0 += bias[col]; v1 += bias[col + 1]; }
                if (GELU_ACT) {
                    v0 = 0.5f * v0 * (1.0f + erff(v0 * 0.70710678118654752f));
                    v1 = 0.5f * v1 * (1.0f + erff(v1 * 0.70710678118654752f));
                }
                size_t idx = (size_t)row * N + col;
                if (NRES >= 1) { v0 += r1[idx]; v1 += r1[idx + 1]; }
                if (NRES >= 2) {
                    v0 += __half2float(r2[idx]);
                    v1 += __half2float(r2[idx + 1]);
                }
                if (HALF_OUT) {
                    *(__half2*)&((__half*)CoutV)[idx] = __floats2half2_rn(v0, v1);
                } else {
                    *(float2*)&((float*)CoutV)[idx] = make_float2(v0, v1);
                }
            }
        }
    }
}

// ---------------- fused flash attention, full fp16 mma ---------------------
// One CTA per (64-query tile, b*h). 128 threads = 4 warps; warp owns 16 rows.
// Smem rows 72 halves = 36 words: bank(4*gid + tig) all distinct; P stays in
// registers (S output pairs ARE the PV A-fragment pairs).
constexpr int AW = 36;  // words per smem row

__global__ __launch_bounds__(128) void attn_h_kernel() {
    __shared__ uint32_t Qs[64 * AW];
    __shared__ uint32_t Ks[64 * AW];
    __shared__ uint32_t Vs[64 * AW];   // V^T tile: [d][kv]

    const int tid = threadIdx.x;
    const int bh = blockIdx.y, b = bh / NH, h = bh - b * NH;
    const int q0 = blockIdx.x * 64;
    const int warp = tid >> 5, lane = tid & 31;
    const int gid = lane >> 2, tig = lane & 3;
    const int r0 = warp * 16 + gid;

    const __half* qb = g_qkvh + (size_t)b * SEQ * C3 + h * HD;
    const __half* kb = qb + C;
    const __half* vtb = g_vth + (size_t)bh * HD * SEQ;

    // load Q tile (64x64 half), pre-scaled by 1/8 (exact in half)
    {
        int row = tid >> 1, w0 = (tid & 1) * 16;
        const __half* src = qb + (size_t)(q0 + row) * C3 + w0 * 2;
        const __half2 sc = __float2half2_rn(0.125f);
#pragma unroll
        for (int j = 0; j < 16; j++) {
            __half2 v = *(const __half2*)(src + j * 2);
            v = __hmul2(v, sc);
            Qs[row * AW + w0 + j] = *(uint32_t*)&v;
        }
    }
    __syncthreads();

    // preload Q A-fragments: 4 k16-steps x 4 regs
    uint32_t qf[4][4];
#pragma unroll
    for (int kt = 0; kt < 4; kt++) {
        qf[kt][0] = Qs[r0 * AW + 8 * kt + tig];
        qf[kt][1] = Qs[(r0 + 8) * AW + 8 * kt + tig];
        qf[kt][2] = Qs[r0 * AW + 8 * kt + tig + 4];
        qf[kt][3] = Qs[(r0 + 8) * AW + 8 * kt + tig + 4];
    }

    float acc_o[8][4] = {};
    float m0r = -1e30f, m1r = -1e30f, l0 = 0.f, l1 = 0.f;

    for (int kv0 = 0; kv0 < SEQ; kv0 += 64) {
        __syncthreads();   // prior iter done reading Ks/Vs
        {
            int row = tid >> 1, w0 = (tid & 1) * 16;
            const __half* ks = kb + (size_t)(kv0 + row) * C3 + w0 * 2;
            const __half* vs = vtb + (size_t)row * SEQ + kv0 + w0 * 2;
#pragma unroll
            for (int j = 0; j < 16; j += 4) {
                *(uint4*)&Ks[row * AW + w0 + j] = *(const uint4*)(ks + j * 2);
                *(uint4*)&Vs[row * AW + w0 + j] = *(const uint4*)(vs + j * 2);
            }
        }
        __syncthreads();

        // S = (Q/8) K^T   (fp32 accum)
        float s[8][4] = {};
#pragma unroll
        for (int kt = 0; kt < 4; kt++) {
            uint32_t bf[8][2];
#pragma unroll
            for (int nt = 0; nt < 8; nt++) {
                int n = nt * 8 + gid;
                bf[nt][0] = Ks[n * AW + 8 * kt + tig];
                bf[nt][1] = Ks[n * AW + 8 * kt + tig + 4];
            }
#pragma unroll
            for (int nt = 0; nt < 8; nt++)
                mma_f16(s[nt], qf[kt], bf[nt]);
        }

        // online softmax (rows r0, r0+8); reduce over 4 tig lanes
        float mx0 = -1e30f, mx1 = -1e30f;
#pragma unroll
        for (int nt = 0; nt < 8; nt++) {
            mx0 = fmaxf(mx0, fmaxf(s[nt][0], s[nt][1]));
            mx1 = fmaxf(mx1, fmaxf(s[nt][2], s[nt][3]));
        }
        mx0 = fmaxf(mx0, __shfl_xor_sync(0xffffffffu, mx0, 1));
        mx0 = fmaxf(mx0, __shfl_xor_sync(0xffffffffu, mx0, 2));
        mx1 = fmaxf(mx1, __shfl_xor_sync(0xffffffffu, mx1, 1));
        mx1 = fmaxf(mx1, __shfl_xor_sync(0xffffffffu, mx1, 2));
        float mn0 = fmaxf(m0r, mx0), mn1 = fmaxf(m1r, mx1);
        float cr0 = __expf(m0r - mn0), cr1 = __expf(m1r - mn1);
        m0r = mn0; m1r = mn1;
        float sum0 = 0.f, sum1 = 0.f;
#pragma unroll
        for (int nt = 0; nt < 8; nt++) {
            s[nt][0] = __expf(s[nt][0] - mn0); sum0 += s[nt][0];
            s[nt][1] = __expf(s[nt][1] - mn0); sum0 += s[nt][1];
            s[nt][2] = __expf(s[nt][2] - mn1); sum1 += s[nt][2];
            s[nt][3] = __expf(s[nt][3] - mn1); sum1 += s[nt][3];
        }
        sum0 += __shfl_xor_sync(0xffffffffu, sum0, 1);
        sum0 += __shfl_xor_sync(0xffffffffu, sum0, 2);
        sum1 += __shfl_xor_sync(0xffffffffu, sum1, 1);
        sum1 += __shfl_xor_sync(0xffffffffu, sum1, 2);
        l0 = l0 * cr0 + sum0;
        l1 = l1 * cr1 + sum1;
#pragma unroll
        for (int nt = 0; nt < 8; nt++) {
            acc_o[nt][0] *= cr0; acc_o[nt][1] *= cr0;
            acc_o[nt][2] *= cr1; acc_o[nt][3] *= cr1;
        }

        // P -> half2 A-fragments directly in registers:
        // S pairs (row, col = nt*8 + 2*tig) == PV A pairs (k = 16*kt + 2*tig)
        // for nt = 2kt (a0/a1) and nt = 2kt+1 (a2/a3).
#pragma unroll
        for (int kt = 0; kt < 4; kt++) {
            __half2 a0 = __floats2half2_rn(s[2 * kt][0], s[2 * kt][1]);
            __half2 a1 = __floats2half2_rn(s[2 * kt][2], s[2 * kt][3]);
            __half2 a2 = __floats2half2_rn(s[2 * kt + 1][0], s[2 * kt + 1][1]);
            __half2 a3 = __floats2half2_rn(s[2 * kt + 1][2], s[2 * kt + 1][3]);
            uint32_t pf[4] = {*(uint32_t*)&a0, *(uint32_t*)&a1,
                              *(uint32_t*)&a2, *(uint32_t*)&a3};
            uint32_t bf[8][2];
#pragma unroll
            for (int nt = 0; nt < 8; nt++) {
                int n = nt * 8 + gid;            // d column
                bf[nt][0] = Vs[n * AW + 8 * kt + tig];
                bf[nt][1] = Vs[n * AW + 8 * kt + tig + 4];
            }
#pragma unroll
            for (int nt = 0; nt < 8; nt++)
                mma_f16(acc_o[nt], pf, bf[nt]);
        }
    }

    // normalize + write half [token, h*64 + d]
    float inv0 = 1.0f / l0, inv1 = 1.0f / l1;
    size_t row0 = (size_t)(b * SEQ + q0 + r0);
#pragma unroll
    for (int nt = 0; nt < 8; nt++) {
        int col = h * HD + nt * 8 + 2 * tig;
        *(__half2*)&g_attnh[row0 * C + col] =
            __floats2half2_rn(acc_o[nt][0] * inv0, acc_o[nt][1] * inv0);
        *(__half2*)&g_attnh[(row0 + 8) * C + col] =
            __floats2half2_rn(acc_o[nt][2] * inv1, acc_o[nt][3] * inv1);
    }
}

// ---------------- launch ---------------------------------------------------
extern "C" void kernel_launch(void* const* d_in, const int* in_sizes, int n_in,
                              void* d_out, int out_size) {
    const float* x    = (const float*)d_in[0];
    const float* ln1g = (const float*)d_in[1];
    const float* ln1b = (const float*)d_in[2];
    const float* wqkv = (const float*)d_in[3];
    const float* wout = (const float*)d_in[4];
    const float* bout = (const float*)d_in[5];
    const float* ln2g = (const float*)d_in[6];
    const float* ln2b = (const float*)d_in[7];
    const float* w1   = (const float*)d_in[8];
    const float* b1   = (const float*)d_in[9];
    const float* w2   = (const float*)d_in[10];
    const float* b2   = (const float*)d_in[11];
    float* out = (float*)d_out;

    __half *h1h, *qkvh, *attnh, *h2h, *midh, *wtqkv, *wtout, *wt1, *wt2;
    float *x1p;
    cudaGetSymbolAddress((void**)&h1h,   g_h1h);
    cudaGetSymbolAddress((void**)&qkvh,  g_qkvh);
    cudaGetSymbolAddress((void**)&attnh, g_attnh);
    cudaGetSymbolAddress((void**)&x1p,   g_x1);
    cudaGetSymbolAddress((void**)&h2h,   g_h2h);
    cudaGetSymbolAddress((void**)&midh,  g_midh);
    cudaGetSymbolAddress((void**)&wtqkv, g_wtqkv);
    cudaGetSymbolAddress((void**)&wtout, g_wtout);
    cudaGetSymbolAddress((void**)&wt1,   g_wt1);
    cudaGetSymbolAddress((void**)&wt2,   g_wt2);

    cudaFuncSetAttribute(gemm_h<false, false, 0, true>,
                         cudaFuncAttributeMaxDynamicSharedMemorySize, GEMM_SMEM);
    cudaFuncSetAttribute(gemm_h<true, false, 2, false>,
                         cudaFuncAttributeMaxDynamicSharedMemorySize, GEMM_SMEM);
    cudaFuncSetAttribute(gemm_h<true, true, 0, true>,
                         cudaFuncAttributeMaxDynamicSharedMemorySize, GEMM_SMEM);
    cudaFuncSetAttribute(gemm_h<true, false, 1, false>,
                         cudaFuncAttributeMaxDynamicSharedMemorySize, GEMM_SMEM);

    dim3 tb(32, 8);
    // 0) transpose+convert weights to half [N][K]
    transpose_cvt_kernel<<<dim3(C3 / 32, C / 32), tb>>>(wqkv, wtqkv, C, C3);
    transpose_cvt_kernel<<<dim3(C / 32, C / 32), tb>>>(wout, wtout, C, C);
    transpose_cvt_kernel<<<dim3(MD / 32, C / 32), tb>>>(w1, wt1, C, MD);
    transpose_cvt_kernel<<<dim3(C / 32, MD / 32), tb>>>(w2, wt2, MD, C);
    // 1) h = LN1(x)  (half out)
    ln_kernel<<<TOK, 256>>>(x, ln1g, ln1b, h1h);
    // 2) qkv = h @ w_qkv  (half out)
    gemm_h<false, false, 0, true><<<dim3(C3 / 128, TOK / 128), 256, GEMM_SMEM>>>(
        h1h, wtqkv, nullptr, nullptr, nullptr, qkvh, C3, C);
    // 2b) V^T per head
    vt_kernel<<<dim3(HD / 32, SEQ / 32, BH), tb>>>();
    // 3) fused attention (full fp16 mma)
    attn_h_kernel<<<dim3(SEQ / 64, BH), 128>>>();
    // 4) x1 = x + h + attn @ w_out + b_out
    gemm_h<true, false, 2, false><<<dim3(C / 128, TOK / 128), 256, GEMM_SMEM>>>(
        attnh, wtout, bout, x, h1h, x1p, C, C);
    // 5) h2 = LN2(x1)  (half out)
    ln_kernel<<<TOK, 256>>>(x1p, ln2g, ln2b, h2h);
    // 6) mid = gelu(h2 @ w1 + b1)  (half out)
    gemm_h<true, true, 0, true><<<dim3(MD / 128, TOK / 128), 256, GEMM_SMEM>>>(
        h2h, wt1, b1, nullptr, nullptr, midh, MD, C);
    // 7) out = x1 + mid @ w2 + b2
    gemm_h<true, false, 1, false><<<dim3(C / 128, TOK / 128), 256, GEMM_SMEM>>>(
        midh, wt2, b2, x1p, nullptr, out, C, MD);
}

// round 16
// speedup vs baseline: 2.6824x; 1.1707x over previous
#include <cuda_runtime.h>
#include <cuda_fp16.h>
#include <math.h>
#include <stdint.h>

constexpr int TOK = 4096;   // B*N tokens
constexpr int C   = 768;
constexpr int C3  = 2304;
constexpr int MD  = 3072;
constexpr int NH  = 12;
constexpr int HD  = 64;
constexpr int SEQ = 1024;
constexpr int BH  = 48;     // B*NH

// ---------------- scratch (device globals; no allocation allowed) ----------
__device__ __half g_h1h[TOK * C];      // LN1 out (half)
__device__ __half g_qkvh[TOK * C3];    // qkv (half)
__device__ __half g_vth[BH * HD * SEQ];// V transposed per head: [bh][d][kv]
__device__ __half g_attnh[TOK * C];    // attention out (half)
__device__ float  g_x1[TOK * C];       // post-attn residual (fp32)
__device__ __half g_h2h[TOK * C];      // LN2 out (half)
__device__ __half g_midh[TOK * MD];    // gelu out (half)
// transposed+converted weights, half [N][K]
__device__ __half g_wtqkv[C3 * C];
__device__ __half g_wtout[C * C];
__device__ __half g_wt1[MD * C];
__device__ __half g_wt2[C * MD];

#define CP_ASYNC16(dst, src) \
    asm volatile("cp.async.cg.shared.global [%0], [%1], 16;\n" :: "r"(dst), "l"(src))
#define CP_COMMIT() asm volatile("cp.async.commit_group;\n" ::)
#define CP_WAIT2()  asm volatile("cp.async.wait_group 2;\n" ::)

#define LDSM_X4(r0, r1, r2, r3, addr) \
    asm volatile("ldmatrix.sync.aligned.m8n8.x4.shared.b16 {%0,%1,%2,%3}, [%4];" \
        : "=r"(r0), "=r"(r1), "=r"(r2), "=r"(r3) : "r"(addr))

__device__ __forceinline__ void mma_f16(float* d, const uint32_t* a, const uint32_t* b) {
    asm volatile(
        "mma.sync.aligned.m16n8k16.row.col.f32.f16.f16.f32 "
        "{%0,%1,%2,%3}, {%4,%5,%6,%7}, {%8,%9}, {%0,%1,%2,%3};"
        : "+f"(d[0]), "+f"(d[1]), "+f"(d[2]), "+f"(d[3])
        : "r"(a[0]), "r"(a[1]), "r"(a[2]), "r"(a[3]), "r"(b[0]), "r"(b[1]));
}

// ---------------- weight transpose+convert: out[n][k] = (half)in[k][n] -----
__global__ void transpose_cvt_kernel(const float* __restrict__ in,
                                     __half* __restrict__ out, int K, int N) {
    __shared__ float t[32][33];
    int n = blockIdx.x * 32 + threadIdx.x;
    int k0 = blockIdx.y * 32;
    int const tx = threadIdx.x;
    for (int j = threadIdx.y; j < 32; j += 8)
        t[j][tx] = in[(size_t)(k0 + j) * N + n];
    __syncthreads();
    int k = k0 + tx;
    int nn0 = blockIdx.x * 32;
    for (int j = threadIdx.y; j < 32; j += 8)
        out[(size_t)(nn0 + j) * K + k] = __float2half_rn(t[tx][j]);
}

// ---------------- V transpose: g_qkvh V-part -> g_vth[bh][d][kv] -----------
__global__ void vt_kernel() {
    __shared__ __half t[32][33];
    int bh = blockIdx.z, b = bh / NH, h = bh - b * NH;
    int kv0 = blockIdx.y * 32, d0 = blockIdx.x * 32;
    int tx = threadIdx.x, ty = threadIdx.y;
    for (int j = ty; j < 32; j += 8)
        t[j][tx] = g_qkvh[(size_t)(b * SEQ + kv0 + j) * C3 + 2 * C + h * HD + d0 + tx];
    __syncthreads();
    for (int j = ty; j < 32; j += 8)
        g_vth[(size_t)bh * HD * SEQ + (size_t)(d0 + j) * SEQ + kv0 + tx] = t[tx][j];
}

// ---------------- LayerNorm: fp32 math, half output ------------------------
__global__ void ln_kernel(const float* __restrict__ x, const float* __restrict__ g,
                          const float* __restrict__ b, __half* __restrict__ out) {
    __shared__ float s1[256], s2[256];
    int row = blockIdx.x, t = threadIdx.x;
    const float* xr = x + (size_t)row * C;
    float v0 = xr[t], v1 = xr[t + 256], v2 = xr[t + 512];
    s1[t] = v0 + v1 + v2;
    s2[t] = v0 * v0 + v1 * v1 + v2 * v2;
    __syncthreads();
    for (int o = 128; o > 0; o >>= 1) {
        if (t < o) { s1[t] += s1[t + o]; s2[t] += s2[t + o]; }
        __syncthreads();
    }
    float mean = s1[0] * (1.0f / C);
    float var  = s2[0] * (1.0f / C) - mean * mean;
    float inv  = rsqrtf(var + 1e-5f);
    __half* orow = out + (size_t)row * C;
    orow[t]       = __float2half_rn((v0 - mean) * inv * g[t]       + b[t]);
    orow[t + 256] = __float2half_rn((v1 - mean) * inv * g[t + 256] + b[t + 256]);
    orow[t + 512] = __float2half_rn((v2 - mean) * inv * g[t + 512] + b[t + 512]);
}

// ---------------- FP16 tensor-core GEMM, cp.async 4-stage, ldmatrix --------
constexpr int STAGES = 4;
constexpr int ROW_W = 20;
constexpr int STAGE_W = 128 * ROW_W;
constexpr int GEMM_SMEM = STAGES * 2 * STAGE_W * 4;   // 81920 B

template <bool BIAS, bool GELU_ACT, int NRES, bool HALF_OUT>
__global__ __launch_bounds__(256, 2) void gemm_h(
    const __half* __restrict__ A, const __half* __restrict__ Bt,
    const float* __restrict__ bias, const float* __restrict__ r1,
    const __half* __restrict__ r2, void* __restrict__ CoutV, int N, int K) {
    extern __shared__ uint32_t smem[];
    uint32_t* AsBase = smem;
    uint32_t* BsBase = smem + STAGES * STAGE_W;

    const int tid = threadIdx.x;
    const int m0 = blockIdx.y * 128, n0 = blockIdx.x * 128;
    const int warp = tid >> 5, lane = tid & 31;
    const int wm = warp & 3, wn = warp >> 2;
    const int gid = lane >> 2, tig = lane & 3;
    const int lm = lane & 7, sel = lane >> 3;

    const int lrow = tid >> 1;
    const int lseg = (tid & 1) * 16;

    const __half* ag = A  + (size_t)(m0 + lrow) * K + lseg;
    const __half* bg = Bt + (size_t)(n0 + lrow) * K + lseg;
    const uint32_t da0 = (uint32_t)__cvta_generic_to_shared(AsBase) + lrow * 80 + lseg * 2;
    const uint32_t db0 = (uint32_t)__cvta_generic_to_shared(BsBase) + lrow * 80 + lseg * 2;

    // ldmatrix per-lane address bases
    // A: matrices a0..a3 = (row gid / gid+8) x (k0-7 / k8-15)
    const uint32_t aLdsm = (uint32_t)__cvta_generic_to_shared(AsBase)
        + (uint32_t)(wm * 32 + lm + (sel & 1) * 8) * 80 + (sel >> 1) * 16;
    // B: matrices r0..r3 = (n block lo/hi within pair) x (k0-7 / k8-15)
    const uint32_t bLdsm = (uint32_t)__cvta_generic_to_shared(BsBase)
        + (uint32_t)(wn * 64 + lm + (sel >> 1) * 8) * 80 + (sel & 1) * 16;

    float acc[2][8][4] = {};

    auto issue_stage = [&](int s, int k0) {
        uint32_t da = da0 + s * (STAGE_W * 4);
        const __half* ap = ag + k0;
        CP_ASYNC16(da, ap);
        CP_ASYNC16(da + 16, ap + 8);
        uint32_t db = db0 + s * (STAGE_W * 4);
        const __half* bp = bg + k0;
        CP_ASYNC16(db, bp);
        CP_ASYNC16(db + 16, bp + 8);
    };

    auto mma_stage = [&](int s) {
        const uint32_t soff = s * (STAGE_W * 4);
#pragma unroll
        for (int kc2 = 0; kc2 < 16; kc2 += 8) {   // k16 step, word units
            uint32_t af[2][4], bf[8][2];
#pragma unroll
            for (int mt = 0; mt < 2; mt++)
                LDSM_X4(af[mt][0], af[mt][1], af[mt][2], af[mt][3],
                        aLdsm + soff + mt * (16 * 80) + kc2 * 4);
#pragma unroll
            for (int p = 0; p < 4; p++)
                LDSM_X4(bf[2 * p][0], bf[2 * p][1], bf[2 * p + 1][0], bf[2 * p + 1][1],
                        bLdsm + soff + p * (16 * 80) + kc2 * 4);
#pragma unroll
            for (int mt = 0; mt < 2; mt++)
#pragma unroll
                for (int nt = 0; nt < 8; nt++)
                    mma_f16(acc[mt][nt], af[mt], bf[nt]);
        }
    };

    const int nk = K / 32;
#pragma unroll
    for (int s = 0; s < STAGES - 1; s++) {
        issue_stage(s, s * 32);
        CP_COMMIT();
    }
    for (int i = 0; i < nk; i++) {
        CP_WAIT2();
        __syncthreads();
        int kn = (i + STAGES - 1) * 32;
        if (kn < K) issue_stage((i + STAGES - 1) & (STAGES - 1), kn);
        CP_COMMIT();
        mma_stage(i & (STAGES - 1));
    }

#pragma unroll
    for (int mt = 0; mt < 2; mt++) {
        int r0 = m0 + wm * 32 + mt * 16 + gid;
#pragma unroll
        for (int nt = 0; nt < 8; nt++) {
            int col = n0 + wn * 64 + nt * 8 + tig * 2;
#pragma unroll
            for (int half_i = 0; half_i < 2; half_i++) {
                int row = r0 + half_i * 8;
                float v0 = acc[mt][nt][half_i * 2 + 0];
                float v1 = acc[mt][nt][half_i * 2 + 1];
                if (BIAS) { v0 += bias[col]; v1 += bias[col + 1]; }
                if (GELU_ACT) {
                    v0 = 0.5f * v0 * (1.0f + erff(v0 * 0.70710678118654752f));
                    v1 = 0.5f * v1 * (1.0f + erff(v1 * 0.70710678118654752f));
                }
                size_t idx = (size_t)row * N + col;
                if (NRES >= 1) { v0 += r1[idx]; v1 += r1[idx + 1]; }
                if (NRES >= 2) {
                    v0 += __half2float(r2[idx]);
                    v1 += __half2float(r2[idx + 1]);
                }
                if (HALF_OUT) {
                    *(__half2*)&((__half*)CoutV)[idx] = __floats2half2_rn(v0, v1);
                } else {
                    *(float2*)&((float*)CoutV)[idx] = make_float2(v0, v1);
                }
            }
        }
    }
}

// ---------------- fused flash attention, full fp16 mma + ldmatrix ----------
constexpr int AW = 36;  // words per smem row (72 halves)

__global__ __launch_bounds__(128) void attn_h_kernel() {
    __shared__ uint32_t Qs[64 * AW];
    __shared__ uint32_t Ks[64 * AW];
    __shared__ uint32_t Vs[64 * AW];   // V^T tile: [d][kv]

    const int tid = threadIdx.x;
    const int bh = blockIdx.y, b = bh / NH, h = bh - b * NH;
    const int q0 = blockIdx.x * 64;
    const int warp = tid >> 5, lane = tid & 31;
    const int gid = lane >> 2, tig = lane & 3;
    const int lm = lane & 7, sel = lane >> 3;
    const int r0 = warp * 16 + gid;

    const __half* qb = g_qkvh + (size_t)b * SEQ * C3 + h * HD;
    const __half* kb = qb + C;
    const __half* vtb = g_vth + (size_t)bh * HD * SEQ;

    // ldmatrix B-address bases (rows = n for K, d for V^T)
    const uint32_t kLdsm = (uint32_t)__cvta_generic_to_shared(Ks)
        + (uint32_t)(lm + (sel >> 1) * 8) * (AW * 4) + (sel & 1) * 16;
    const uint32_t vLdsm = (uint32_t)__cvta_generic_to_shared(Vs)
        + (uint32_t)(lm + (sel >> 1) * 8) * (AW * 4) + (sel & 1) * 16;

    // load Q tile (64x64 half), pre-scaled by 1/8 (exact in half)
    {
        int row = tid >> 1, w0 = (tid & 1) * 16;
        const __half* src = qb + (size_t)(q0 + row) * C3 + w0 * 2;
        const __half2 sc = __float2half2_rn(0.125f);
#pragma unroll
        for (int j = 0; j < 16; j++) {
            __half2 v = *(const __half2*)(src + j * 2);
            v = __hmul2(v, sc);
            Qs[row * AW + w0 + j] = *(uint32_t*)&v;
        }
    }
    __syncthreads();

    // preload Q A-fragments: 4 k16-steps x 4 regs
    uint32_t qf[4][4];
#pragma unroll
    for (int kt = 0; kt < 4; kt++) {
        qf[kt][0] = Qs[r0 * AW + 8 * kt + tig];
        qf[kt][1] = Qs[(r0 + 8) * AW + 8 * kt + tig];
        qf[kt][2] = Qs[r0 * AW + 8 * kt + tig + 4];
        qf[kt][3] = Qs[(r0 + 8) * AW + 8 * kt + tig + 4];
    }

    float acc_o[8][4] = {};
    float m0r = -1e30f, m1r = -1e30f, l0 = 0.f, l1 = 0.f;

    for (int kv0 = 0; kv0 < SEQ; kv0 += 64) {
        __syncthreads();
        {
            int row = tid >> 1, w0 = (tid & 1) * 16;
            const __half* ks = kb + (size_t)(kv0 + row) * C3 + w0 * 2;
            const __half* vs = vtb + (size_t)row * SEQ + kv0 + w0 * 2;
#pragma unroll
            for (int j = 0; j < 16; j += 4) {
                *(uint4*)&Ks[row * AW + w0 + j] = *(const uint4*)(ks + j * 2);
                *(uint4*)&Vs[row * AW + w0 + j] = *(const uint4*)(vs + j * 2);
            }
        }
        __syncthreads();

        // S = (Q/8) K^T
        float s[8][4] = {};
#pragma unroll
        for (int kt = 0; kt < 4; kt++) {
            uint32_t bf[8][2];
#pragma unroll
            for (int p = 0; p < 4; p++)
                LDSM_X4(bf[2 * p][0], bf[2 * p][1], bf[2 * p + 1][0], bf[2 * p + 1][1],
                        kLdsm + p * (16 * AW * 4) + kt * 32);
#pragma unroll
            for (int nt = 0; nt < 8; nt++)
                mma_f16(s[nt], qf[kt], bf[nt]);
        }

        // online softmax (rows r0, r0+8); reduce over 4 tig lanes
        float mx0 = -1e30f, mx1 = -1e30f;
#pragma unroll
        for (int nt = 0; nt < 8; nt++) {
            mx0 = fmaxf(mx0, fmaxf(s[nt][0], s[nt][1]));
            mx1 = fmaxf(mx1, fmaxf(s[nt][2], s[nt][3]));
        }
        mx0 = fmaxf(mx0, __shfl_xor_sync(0xffffffffu, mx0, 1));
        mx0 = fmaxf(mx0, __shfl_xor_sync(0xffffffffu, mx0, 2));
        mx1 = fmaxf(mx1, __shfl_xor_sync(0xffffffffu, mx1, 1));
        mx1 = fmaxf(mx1, __shfl_xor_sync(0xffffffffu, mx1, 2));
        float mn0 = fmaxf(m0r, mx0), mn1 = fmaxf(m1r, mx1);
        float cr0 = __expf(m0r - mn0), cr1 = __expf(m1r - mn1);
        m0r = mn0; m1r = mn1;
        float sum0 = 0.f, sum1 = 0.f;
#pragma unroll
        for (int nt = 0; nt < 8; nt++) {
            s[nt][0] = __expf(s[nt][0] - mn0); sum0 += s[nt][0];
            s[nt][1] = __expf(s[nt][1] - mn0); sum0 += s[nt][1];
            s[nt][2] = __expf(s[nt][2] - mn1); sum1 += s[nt][2];
            s[nt][3] = __expf(s[nt][3] - mn1); sum1 += s[nt][3];
        }
        sum0 += __shfl_xor_sync(0xffffffffu, sum0, 1);
        sum0 += __shfl_xor_sync(0xffffffffu, sum0, 2);
        sum1 += __shfl_xor_sync(0xffffffffu, sum1, 1);
        sum1 += __shfl_xor_sync(0xffffffffu, sum1, 2);
        l0 = l0 * cr0 + sum0;
        l1 = l1 * cr1 + sum1;
#pragma unroll
        for (int nt = 0; nt < 8; nt++) {
            acc_o[nt][0] *= cr0; acc_o[nt][1] *= cr0;
            acc_o[nt][2] *= cr1; acc_o[nt][3] *= cr1;
        }

        // P stays in registers: S pairs == PV A-fragment pairs
#pragma unroll
        for (int kt = 0; kt < 4; kt++) {
            __half2 a0 = __floats2half2_rn(s[2 * kt][0], s[2 * kt][1]);
            __half2 a1 = __floats2half2_rn(s[2 * kt][2], s[2 * kt][3]);
            __half2 a2 = __floats2half2_rn(s[2 * kt + 1][0], s[2 * kt + 1][1]);
            __half2 a3 = __floats2half2_rn(s[2 * kt + 1][2], s[2 * kt + 1][3]);
            uint32_t pf[4] = {*(uint32_t*)&a0, *(uint32_t*)&a1,
                              *(uint32_t*)&a2, *(uint32_t*)&a3};
            uint32_t bf[8][2];
#pragma unroll
            for (int p = 0; p < 4; p++)
                LDSM_X4(bf[2 * p][0], bf[2 * p][1], bf[2 * p + 1][0], bf[2 * p + 1][1],
                        vLdsm + p * (16 * AW * 4) + kt * 32);
#pragma unroll
            for (int nt = 0; nt < 8; nt++)
                mma_f16(acc_o[nt], pf, bf[nt]);
        }
    }

    // normalize + write half [token, h*64 + d]
    float inv0 = 1.0f / l0, inv1 = 1.0f / l1;
    size_t row0 = (size_t)(b * SEQ + q0 + r0);
#pragma unroll
    for (int nt = 0; nt < 8; nt++) {
        int col = h * HD + nt * 8 + 2 * tig;
        *(__half2*)&g_attnh[row0 * C + col] =
            __floats2half2_rn(acc_o[nt][0] * inv0, acc_o[nt][1] * inv0);
        *(__half2*)&g_attnh[(row0 + 8) * C + col] =
            __floats2half2_rn(acc_o[nt][2] * inv1, acc_o[nt][3] * inv1);
    }
}

// ---------------- launch ---------------------------------------------------
extern "C" void kernel_launch(void* const* d_in, const int* in_sizes, int n_in,
                              void* d_out, int out_size) {
    const float* x    = (const float*)d_in[0];
    const float* ln1g = (const float*)d_in[1];
    const float* ln1b = (const float*)d_in[2];
    const float* wqkv = (const float*)d_in[3];
    const float* wout = (const float*)d_in[4];
    const float* bout = (const float*)d_in[5];
    const float* ln2g = (const float*)d_in[6];
    const float* ln2b = (const float*)d_in[7];
    const float* w1   = (const float*)d_in[8];
    const float* b1   = (const float*)d_in[9];
    const float* w2   = (const float*)d_in[10];
    const float* b2   = (const float*)d_in[11];
    float* out = (float*)d_out;

    __half *h1h, *qkvh, *attnh, *h2h, *midh, *wtqkv, *wtout, *wt1, *wt2;
    float *x1p;
    cudaGetSymbolAddress((void**)&h1h,   g_h1h);
    cudaGetSymbolAddress((void**)&qkvh,  g_qkvh);
    cudaGetSymbolAddress((void**)&attnh, g_attnh);
    cudaGetSymbolAddress((void**)&x1p,   g_x1);
    cudaGetSymbolAddress((void**)&h2h,   g_h2h);
    cudaGetSymbolAddress((void**)&midh,  g_midh);
    cudaGetSymbolAddress((void**)&wtqkv, g_wtqkv);
    cudaGetSymbolAddress((void**)&wtout, g_wtout);
    cudaGetSymbolAddress((void**)&wt1,   g_wt1);
    cudaGetSymbolAddress((void**)&wt2,   g_wt2);

    cudaFuncSetAttribute(gemm_h<false, false, 0, true>,
                         cudaFuncAttributeMaxDynamicSharedMemorySize, GEMM_SMEM);
    cudaFuncSetAttribute(gemm_h<true, false, 2, false>,
                         cudaFuncAttributeMaxDynamicSharedMemorySize, GEMM_SMEM);
    cudaFuncSetAttribute(gemm_h<true, true, 0, true>,
                         cudaFuncAttributeMaxDynamicSharedMemorySize, GEMM_SMEM);
    cudaFuncSetAttribute(gemm_h<true, false, 1, false>,
                         cudaFuncAttributeMaxDynamicSharedMemorySize, GEMM_SMEM);

    dim3 tb(32, 8);
    // 0) transpose+convert weights to half [N][K]
    transpose_cvt_kernel<<<dim3(C3 / 32, C / 32), tb>>>(wqkv, wtqkv, C, C3);
    transpose_cvt_kernel<<<dim3(C / 32, C / 32), tb>>>(wout, wtout, C, C);
    transpose_cvt_kernel<<<dim3(MD / 32, C / 32), tb>>>(w1, wt1, C, MD);
    transpose_cvt_kernel<<<dim3(C / 32, MD / 32), tb>>>(w2, wt2, MD, C);
    // 1) h = LN1(x)  (half out)
    ln_kernel<<<TOK, 256>>>(x, ln1g, ln1b, h1h);
    // 2) qkv = h @ w_qkv  (half out)
    gemm_h<false, false, 0, true><<<dim3(C3 / 128, TOK / 128), 256, GEMM_SMEM>>>(
        h1h, wtqkv, nullptr, nullptr, nullptr, qkvh, C3, C);
    // 2b) V^T per head
    vt_kernel<<<dim3(HD / 32, SEQ / 32, BH), tb>>>();
    // 3) fused attention (full fp16 mma)
    attn_h_kernel<<<dim3(SEQ / 64, BH), 128>>>();
    // 4) x1 = x + h + attn @ w_out + b_out
    gemm_h<true, false, 2, false><<<dim3(C / 128, TOK / 128), 256, GEMM_SMEM>>>(
        attnh, wtout, bout, x, h1h, x1p, C, C);
    // 5) h2 = LN2(x1)  (half out)
    ln_kernel<<<TOK, 256>>>(x1p, ln2g, ln2b, h2h);
    // 6) mid = gelu(h2 @ w1 + b1)  (half out)
    gemm_h<true, true, 0, true><<<dim3(MD / 128, TOK / 128), 256, GEMM_SMEM>>>(
        h2h, wt1, b1, nullptr, nullptr, midh, MD, C);
    // 7) out = x1 + mid @ w2 + b2
    gemm_h<true, false, 1, false><<<dim3(C / 128, TOK / 128), 256, GEMM_SMEM>>>(
        midh, wt2, b2, x1p, nullptr, out, C, MD);
}

// round 17
// speedup vs baseline: 2.8269x; 1.0539x over previous
#include <cuda_runtime.h>
#include <cuda_fp16.h>
#include <math.h>
#include <stdint.h>

constexpr int TOK = 4096;   // B*N tokens
constexpr int C   = 768;
constexpr int C3  = 2304;
constexpr int MD  = 3072;
constexpr int NH  = 12;
constexpr int HD  = 64;
constexpr int SEQ = 1024;
constexpr int BH  = 48;     // B*NH

// ---------------- scratch (device globals; no allocation allowed) ----------
__device__ __half g_h1h[TOK * C];      // LN1 out (half)
__device__ __half g_qkvh[TOK * C3];    // qkv (half)
__device__ __half g_vth[BH * HD * SEQ];// V transposed per head: [bh][d][kv]
__device__ __half g_attnh[TOK * C];    // attention out (half)
__device__ float  g_x1[TOK * C];       // post-attn residual (fp32)
__device__ __half g_h2h[TOK * C];      // LN2 out (half)
__device__ __half g_midh[TOK * MD];    // gelu out (half)
// transposed+converted weights, half [N][K]
__device__ __half g_wtqkv[C3 * C];
__device__ __half g_wtout[C * C];
__device__ __half g_wt1[MD * C];
__device__ __half g_wt2[C * MD];

#define CP_ASYNC16(dst, src) \
    asm volatile("cp.async.cg.shared.global [%0], [%1], 16;\n" :: "r"(dst), "l"(src))
#define CP_COMMIT() asm volatile("cp.async.commit_group;\n" ::)
#define CP_WAIT2()  asm volatile("cp.async.wait_group 2;\n" ::)

#define LDSM_X4(r0, r1, r2, r3, addr) \
    asm volatile("ldmatrix.sync.aligned.m8n8.x4.shared.b16 {%0,%1,%2,%3}, [%4];" \
        : "=r"(r0), "=r"(r1), "=r"(r2), "=r"(r3) : "r"(addr))

__device__ __forceinline__ void mma_f16(float* d, const uint32_t* a, const uint32_t* b) {
    asm volatile(
        "mma.sync.aligned.m16n8k16.row.col.f32.f16.f16.f32 "
        "{%0,%1,%2,%3}, {%4,%5,%6,%7}, {%8,%9}, {%0,%1,%2,%3};"
        : "+f"(d[0]), "+f"(d[1]), "+f"(d[2]), "+f"(d[3])
        : "r"(a[0]), "r"(a[1]), "r"(a[2]), "r"(a[3]), "r"(b[0]), "r"(b[1]));
}

// ---------------- weight transpose+convert: out[n][k] = (half)in[k][n] -----
// 32x32 tile. Phase 1: float4 gmem loads -> smem (scalar scatter, banks
// ty+4tx+i all distinct). Phase 2: 128 threads, 8 cvt + one 16B STG each
// (smem banks 8c+i+n all distinct).
__global__ void transpose_cvt_kernel(const float* __restrict__ in,
                                     __half* __restrict__ out, int K, int N) {
    __shared__ float t[32][33];
    const int tx = threadIdx.x;          // 0..7
    const int ty = threadIdx.y;          // 0..31
    const int n0 = blockIdx.x * 32, k0 = blockIdx.y * 32;

    float4 rd = *(const float4*)&in[(size_t)(k0 + ty) * N + n0 + tx * 4];
    t[ty][tx * 4 + 0] = rd.x;
    t[ty][tx * 4 + 1] = rd.y;
    t[ty][tx * 4 + 2] = rd.z;
    t[ty][tx * 4 + 3] = rd.w;
    __syncthreads();

    const int tid = ty * 8 + tx;         // 0..255
    if (tid < 128) {
        const int n = tid >> 2;          // 0..31
        const int c = tid & 3;           // 0..3 (8-k chunk)
        __half h[8];
#pragma unroll
        for (int i = 0; i < 8; i++)
            h[i] = __float2half_rn(t[c * 8 + i][n]);
        *(uint4*)&out[(size_t)(n0 + n) * K + k0 + c * 8] = *(uint4*)h;
    }
}

// ---------------- V transpose: g_qkvh V-part -> g_vth[bh][d][kv] -----------
__global__ void vt_kernel() {
    __shared__ __half t[32][33];
    int bh = blockIdx.z, b = bh / NH, h = bh - b * NH;
    int kv0 = blockIdx.y * 32, d0 = blockIdx.x * 32;
    int tx = threadIdx.x, ty = threadIdx.y;
    for (int j = ty; j < 32; j += 8)
        t[j][tx] = g_qkvh[(size_t)(b * SEQ + kv0 + j) * C3 + 2 * C + h * HD + d0 + tx];
    __syncthreads();
    for (int j = ty; j < 32; j += 8)
        g_vth[(size_t)bh * HD * SEQ + (size_t)(d0 + j) * SEQ + kv0 + tx] = t[tx][j];
}

// ---------------- LayerNorm: 192 thr, float4 loads, half2 stores -----------
__global__ void ln_kernel(const float* __restrict__ x, const float* __restrict__ g,
                          const float* __restrict__ b, __half* __restrict__ out) {
    __shared__ float ps[6], qs[6];
    const int row = blockIdx.x, t = threadIdx.x;   // 192 threads
    const int warp = t >> 5, lane = t & 31;

    float4 v = *(const float4*)&x[(size_t)row * C + t * 4];
    float s = v.x + v.y + v.z + v.w;
    float q = v.x * v.x + v.y * v.y + v.z * v.z + v.w * v.w;
#pragma unroll
    for (int o = 16; o > 0; o >>= 1) {
        s += __shfl_xor_sync(0xffffffffu, s, o);
        q += __shfl_xor_sync(0xffffffffu, q, o);
    }
    if (lane == 0) { ps[warp] = s; qs[warp] = q; }
    __syncthreads();
    float st = ps[0] + ps[1] + ps[2] + ps[3] + ps[4] + ps[5];
    float qt = qs[0] + qs[1] + qs[2] + qs[3] + qs[4] + qs[5];
    float mean = st * (1.0f / C);
    float var  = qt * (1.0f / C) - mean * mean;
    float inv  = rsqrtf(var + 1e-5f);

    float4 gv = *(const float4*)&g[t * 4];
    float4 bv = *(const float4*)&b[t * 4];
    __half2 h0 = __floats2half2_rn((v.x - mean) * inv * gv.x + bv.x,
                                   (v.y - mean) * inv * gv.y + bv.y);
    __half2 h1 = __floats2half2_rn((v.z - mean) * inv * gv.z + bv.z,
                                   (v.w - mean) * inv * gv.w + bv.w);
    uint2 pk;
    pk.x = *(uint32_t*)&h0;
    pk.y = *(uint32_t*)&h1;
    *(uint2*)&out[(size_t)row * C + t * 4] = pk;
}

// ---------------- FP16 tensor-core GEMM, cp.async 4-stage, ldmatrix --------
constexpr int STAGES = 4;
constexpr int ROW_W = 20;
constexpr int STAGE_W = 128 * ROW_W;
constexpr int GEMM_SMEM = STAGES * 2 * STAGE_W * 4;   // 81920 B

template <bool BIAS, bool GELU_ACT, int NRES, bool HALF_OUT>
__global__ __launch_bounds__(256, 2) void gemm_h(
    const __half* __restrict__ A, const __half* __restrict__ Bt,
    const float* __restrict__ bias, const float* __restrict__ r1,
    const __half* __restrict__ r2, void* __restrict__ CoutV, int N, int K) {
    extern __shared__ uint32_t smem[];
    uint32_t* AsBase = smem;
    uint32_t* BsBase = smem + STAGES * STAGE_W;

    const int tid = threadIdx.x;
    const int m0 = blockIdx.y * 128, n0 = blockIdx.x * 128;
    const int warp = tid >> 5, lane = tid & 31;
    const int wm = warp & 3, wn = warp >> 2;
    const int gid = lane >> 2, tig = lane & 3;
    const int lm = lane & 7, sel = lane >> 3;

    const int lrow = tid >> 1;
    const int lseg = (tid & 1) * 16;

    const __half* ag = A  + (size_t)(m0 + lrow) * K + lseg;
    const __half* bg = Bt + (size_t)(n0 + lrow) * K + lseg;
    const uint32_t da0 = (uint32_t)__cvta_generic_to_shared(AsBase) + lrow * 80 + lseg * 2;
    const uint32_t db0 = (uint32_t)__cvta_generic_to_shared(BsBase) + lrow * 80 + lseg * 2;

    const uint32_t aLdsm = (uint32_t)__cvta_generic_to_shared(AsBase)
        + (uint32_t)(wm * 32 + lm + (sel & 1) * 8) * 80 + (sel >> 1) * 16;
    const uint32_t bLdsm = (uint32_t)__cvta_generic_to_shared(BsBase)
        + (uint32_t)(wn * 64 + lm + (sel >> 1) * 8) * 80 + (sel & 1) * 16;

    float acc[2][8][4] = {};

    auto issue_stage = [&](int s, int k0) {
        uint32_t da = da0 + s * (STAGE_W * 4);
        const __half* ap = ag + k0;
        CP_ASYNC16(da, ap);
        CP_ASYNC16(da + 16, ap + 8);
        uint32_t db = db0 + s * (STAGE_W * 4);
        const __half* bp = bg + k0;
        CP_ASYNC16(db, bp);
        CP_ASYNC16(db + 16, bp + 8);
    };

    auto mma_stage = [&](int s) {
        const uint32_t soff = s * (STAGE_W * 4);
#pragma unroll
        for (int kc2 = 0; kc2 < 16; kc2 += 8) {
            uint32_t af[2][4], bf[8][2];
#pragma unroll
            for (int mt = 0; mt < 2; mt++)
                LDSM_X4(af[mt][0], af[mt][1], af[mt][2], af[mt][3],
                        aLdsm + soff + mt * (16 * 80) + kc2 * 4);
#pragma unroll
            for (int p = 0; p < 4; p++)
                LDSM_X4(bf[2 * p][0], bf[2 * p][1], bf[2 * p + 1][0], bf[2 * p + 1][1],
                        bLdsm + soff + p * (16 * 80) + kc2 * 4);
#pragma unroll
            for (int mt = 0; mt < 2; mt++)
#pragma unroll
                for (int nt = 0; nt < 8; nt++)
                    mma_f16(acc[mt][nt], af[mt], bf[nt]);
        }
    };

    const int nk = K / 32;
#pragma unroll
    for (int s = 0; s < STAGES - 1; s++) {
        issue_stage(s, s * 32);
        CP_COMMIT();
    }
    for (int i = 0; i < nk; i++) {
        CP_WAIT2();
        __syncthreads();
        int kn = (i + STAGES - 1) * 32;
        if (kn < K) issue_stage((i + STAGES - 1) & (STAGES - 1), kn);
        CP_COMMIT();
        mma_stage(i & (STAGES - 1));
    }

#pragma unroll
    for (int mt = 0; mt < 2; mt++) {
        int r0 = m0 + wm * 32 + mt * 16 + gid;
#pragma unroll
        for (int nt = 0; nt < 8; nt++) {
            int col = n0 + wn * 64 + nt * 8 + tig * 2;
#pragma unroll
            for (int half_i = 0; half_i < 2; half_i++) {
                int row = r0 + half_i * 8;
                float v0 = acc[mt][nt][half_i * 2 + 0];
                float v1 = acc[mt][nt][half_i * 2 + 1];
                if (BIAS) { v0 += bias[col]; v1 += bias[col + 1]; }
                if (GELU_ACT) {
                    v0 = 0.5f * v0 * (1.0f + erff(v0 * 0.70710678118654752f));
                    v1 = 0.5f * v1 * (1.0f + erff(v1 * 0.70710678118654752f));
                }
                size_t idx = (size_t)row * N + col;
                if (NRES >= 1) { v0 += r1[idx]; v1 += r1[idx + 1]; }
                if (NRES >= 2) {
                    v0 += __half2float(r2[idx]);
                    v1 += __half2float(r2[idx + 1]);
                }
                if (HALF_OUT) {
                    *(__half2*)&((__half*)CoutV)[idx] = __floats2half2_rn(v0, v1);
                } else {
                    *(float2*)&((float*)CoutV)[idx] = make_float2(v0, v1);
                }
            }
        }
    }
}

// ---------------- fused flash attention, full fp16 mma + ldmatrix ----------
constexpr int AW = 36;  // words per smem row (72 halves)

__global__ __launch_bounds__(128) void attn_h_kernel() {
    __shared__ uint32_t Qs[64 * AW];
    __shared__ uint32_t Ks[64 * AW];
    __shared__ uint32_t Vs[64 * AW];   // V^T tile: [d][kv]

    const int tid = threadIdx.x;
    const int bh = blockIdx.y, b = bh / NH, h = bh - b * NH;
    const int q0 = blockIdx.x * 64;
    const int warp = tid >> 5, lane = tid & 31;
    const int gid = lane >> 2, tig = lane & 3;
    const int lm = lane & 7, sel = lane >> 3;
    const int r0 = warp * 16 + gid;

    const __half* qb = g_qkvh + (size_t)b * SEQ * C3 + h * HD;
    const __half* kb = qb + C;
    const __half* vtb = g_vth + (size_t)bh * HD * SEQ;

    const uint32_t kLdsm = (uint32_t)__cvta_generic_to_shared(Ks)
        + (uint32_t)(lm + (sel >> 1) * 8) * (AW * 4) + (sel & 1) * 16;
    const uint32_t vLdsm = (uint32_t)__cvta_generic_to_shared(Vs)
        + (uint32_t)(lm + (sel >> 1) * 8) * (AW * 4) + (sel & 1) * 16;

    {
        int row = tid >> 1, w0 = (tid & 1) * 16;
        const __half* src = qb + (size_t)(q0 + row) * C3 + w0 * 2;
        const __half2 sc = __float2half2_rn(0.125f);
#pragma unroll
        for (int j = 0; j < 16; j++) {
            __half2 v = *(const __half2*)(src + j * 2);
            v = __hmul2(v, sc);
            Qs[row * AW + w0 + j] = *(uint32_t*)&v;
        }
    }
    __syncthreads();

    uint32_t qf[4][4];
#pragma unroll
    for (int kt = 0; kt < 4; kt++) {
        qf[kt][0] = Qs[r0 * AW + 8 * kt + tig];
        qf[kt][1] = Qs[(r0 + 8) * AW + 8 * kt + tig];
        qf[kt][2] = Qs[r0 * AW + 8 * kt + tig + 4];
        qf[kt][3] = Qs[(r0 + 8) * AW + 8 * kt + tig + 4];
    }

    float acc_o[8][4] = {};
    float m0r = -1e30f, m1r = -1e30f, l0 = 0.f, l1 = 0.f;

    for (int kv0 = 0; kv0 < SEQ; kv0 += 64) {
        __syncthreads();
        {
            int row = tid >> 1, w0 = (tid & 1) * 16;
            const __half* ks = kb + (size_t)(kv0 + row) * C3 + w0 * 2;
            const __half* vs = vtb + (size_t)row * SEQ + kv0 + w0 * 2;
#pragma unroll
            for (int j = 0; j < 16; j += 4) {
                *(uint4*)&Ks[row * AW + w0 + j] = *(const uint4*)(ks + j * 2);
                *(uint4*)&Vs[row * AW + w0 + j] = *(const uint4*)(vs + j * 2);
            }
        }
        __syncthreads();

        float s[8][4] = {};
#pragma unroll
        for (int kt = 0; kt < 4; kt++) {
            uint32_t bf[8][2];
#pragma unroll
            for (int p = 0; p < 4; p++)
                LDSM_X4(bf[2 * p][0], bf[2 * p][1], bf[2 * p + 1][0], bf[2 * p + 1][1],
                        kLdsm + p * (16 * AW * 4) + kt * 32);
#pragma unroll
            for (int nt = 0; nt < 8; nt++)
                mma_f16(s[nt], qf[kt], bf[nt]);
        }

        float mx0 = -1e30f, mx1 = -1e30f;
#pragma unroll
        for (int nt = 0; nt < 8; nt++) {
            mx0 = fmaxf(mx0, fmaxf(s[nt][0], s[nt][1]));
            mx1 = fmaxf(mx1, fmaxf(s[nt][2], s[nt][3]));
        }
        mx0 = fmaxf(mx0, __shfl_xor_sync(0xffffffffu, mx0, 1));
        mx0 = fmaxf(mx0, __shfl_xor_sync(0xffffffffu, mx0, 2));
        mx1 = fmaxf(mx1, __shfl_xor_sync(0xffffffffu, mx1, 1));
        mx1 = fmaxf(mx1, __shfl_xor_sync(0xffffffffu, mx1, 2));
        float mn0 = fmaxf(m0r, mx0), mn1 = fmaxf(m1r, mx1);
        float cr0 = __expf(m0r - mn0), cr1 = __expf(m1r - mn1);
        m0r = mn0; m1r = mn1;
        float sum0 = 0.f, sum1 = 0.f;
#pragma unroll
        for (int nt = 0; nt < 8; nt++) {
            s[nt][0] = __expf(s[nt][0] - mn0); sum0 += s[nt][0];
            s[nt][1] = __expf(s[nt][1] - mn0); sum0 += s[nt][1];
            s[nt][2] = __expf(s[nt][2] - mn1); sum1 += s[nt][2];
            s[nt][3] = __expf(s[nt][3] - mn1); sum1 += s[nt][3];
        }
        sum0 += __shfl_xor_sync(0xffffffffu, sum0, 1);
        sum0 += __shfl_xor_sync(0xffffffffu, sum0, 2);
        sum1 += __shfl_xor_sync(0xffffffffu, sum1, 1);
        sum1 += __shfl_xor_sync(0xffffffffu, sum1, 2);
        l0 = l0 * cr0 + sum0;
        l1 = l1 * cr1 + sum1;
#pragma unroll
        for (int nt = 0; nt < 8; nt++) {
            acc_o[nt][0] *= cr0; acc_o[nt][1] *= cr0;
            acc_o[nt][2] *= cr1; acc_o[nt][3] *= cr1;
        }

#pragma unroll
        for (int kt = 0; kt < 4; kt++) {
            __half2 a0 = __floats2half2_rn(s[2 * kt][0], s[2 * kt][1]);
            __half2 a1 = __floats2half2_rn(s[2 * kt][2], s[2 * kt][3]);
            __half2 a2 = __floats2half2_rn(s[2 * kt + 1][0], s[2 * kt + 1][1]);
            __half2 a3 = __floats2half2_rn(s[2 * kt + 1][2], s[2 * kt + 1][3]);
            uint32_t pf[4] = {*(uint32_t*)&a0, *(uint32_t*)&a1,
                              *(uint32_t*)&a2, *(uint32_t*)&a3};
            uint32_t bf[8][2];
#pragma unroll
            for (int p = 0; p < 4; p++)
                LDSM_X4(bf[2 * p][0], bf[2 * p][1], bf[2 * p + 1][0], bf[2 * p + 1][1],
                        vLdsm + p * (16 * AW * 4) + kt * 32);
#pragma unroll
            for (int nt = 0; nt < 8; nt++)
                mma_f16(acc_o[nt], pf, bf[nt]);
        }
    }

    float inv0 = 1.0f / l0, inv1 = 1.0f / l1;
    size_t row0 = (size_t)(b * SEQ + q0 + r0);
#pragma unroll
    for (int nt = 0; nt < 8; nt++) {
        int col = h * HD + nt * 8 + 2 * tig;
        *(__half2*)&g_attnh[row0 * C + col] =
            __floats2half2_rn(acc_o[nt][0] * inv0, acc_o[nt][1] * inv0);
        *(__half2*)&g_attnh[(row0 + 8) * C + col] =
            __floats2half2_rn(acc_o[nt][2] * inv1, acc_o[nt][3] * inv1);
    }
}

// ---------------- launch ---------------------------------------------------
extern "C" void kernel_launch(void* const* d_in, const int* in_sizes, int n_in,
                              void* d_out, int out_size) {
    const float* x    = (const float*)d_in[0];
    const float* ln1g = (const float*)d_in[1];
    const float* ln1b = (const float*)d_in[2];
    const float* wqkv = (const float*)d_in[3];
    const float* wout = (const float*)d_in[4];
    const float* bout = (const float*)d_in[5];
    const float* ln2g = (const float*)d_in[6];
    const float* ln2b = (const float*)d_in[7];
    const float* w1   = (const float*)d_in[8];
    const float* b1   = (const float*)d_in[9];
    const float* w2   = (const float*)d_in[10];
    const float* b2   = (const float*)d_in[11];
    float* out = (float*)d_out;

    __half *h1h, *qkvh, *attnh, *h2h, *midh, *wtqkv, *wtout, *wt1, *wt2;
    float *x1p;
    cudaGetSymbolAddress((void**)&h1h,   g_h1h);
    cudaGetSymbolAddress((void**)&qkvh,  g_qkvh);
    cudaGetSymbolAddress((void**)&attnh, g_attnh);
    cudaGetSymbolAddress((void**)&x1p,   g_x1);
    cudaGetSymbolAddress((void**)&h2h,   g_h2h);
    cudaGetSymbolAddress((void**)&midh,  g_midh);
    cudaGetSymbolAddress((void**)&wtqkv, g_wtqkv);
    cudaGetSymbolAddress((void**)&wtout, g_wtout);
    cudaGetSymbolAddress((void**)&wt1,   g_wt1);
    cudaGetSymbolAddress((void**)&wt2,   g_wt2);

    cudaFuncSetAttribute(gemm_h<false, false, 0, true>,
                         cudaFuncAttributeMaxDynamicSharedMemorySize, GEMM_SMEM);
    cudaFuncSetAttribute(gemm_h<true, false, 2, false>,
                         cudaFuncAttributeMaxDynamicSharedMemorySize, GEMM_SMEM);
    cudaFuncSetAttribute(gemm_h<true, true, 0, true>,
                         cudaFuncAttributeMaxDynamicSharedMemorySize, GEMM_SMEM);
    cudaFuncSetAttribute(gemm_h<true, false, 1, false>,
                         cudaFuncAttributeMaxDynamicSharedMemorySize, GEMM_SMEM);

    dim3 tb8(32, 8);
    dim3 tbT(8, 32);
    // 0) transpose+convert weights to half [N][K]
    transpose_cvt_kernel<<<dim3(C3 / 32, C / 32), tbT>>>(wqkv, wtqkv, C, C3);
    transpose_cvt_kernel<<<dim3(C / 32, C / 32), tbT>>>(wout, wtout, C, C);
    transpose_cvt_kernel<<<dim3(MD / 32, C / 32), tbT>>>(w1, wt1, C, MD);
    transpose_cvt_kernel<<<dim3(C / 32, MD / 32), tbT>>>(w2, wt2, MD, C);
    // 1) h = LN1(x)  (half out)
    ln_kernel<<<TOK, 192>>>(x, ln1g, ln1b, h1h);
    // 2) qkv = h @ w_qkv  (half out)
    gemm_h<false, false, 0, true><<<dim3(C3 / 128, TOK / 128), 256, GEMM_SMEM>>>(
        h1h, wtqkv, nullptr, nullptr, nullptr, qkvh, C3, C);
    // 2b) V^T per head
    vt_kernel<<<dim3(HD / 32, SEQ / 32, BH), tb8>>>();
    // 3) fused attention (full fp16 mma)
    attn_h_kernel<<<dim3(SEQ / 64, BH), 128>>>();
    // 4) x1 = x + h + attn @ w_out + b_out
    gemm_h<true, false, 2, false><<<dim3(C / 128, TOK / 128), 256, GEMM_SMEM>>>(
        attnh, wtout, bout, x, h1h, x1p, C, C);
    // 5) h2 = LN2(x1)  (half out)
    ln_kernel<<<TOK, 192>>>(x1p, ln2g, ln2b, h2h);
    // 6) mid = gelu(h2 @ w1 + b1)  (half out)
    gemm_h<true, true, 0, true><<<dim3(MD / 128, TOK / 128), 256, GEMM_SMEM>>>(
        h2h, wt1, b1, nullptr, nullptr, midh, MD, C);
    // 7) out = x1 + mid @ w2 + b2
    gemm_h<true, false, 1, false><<<dim3(C / 128, TOK / 128), 256, GEMM_SMEM>>>(
        midh, wt2, b2, x1p, nullptr, out, C, MD);
}